// round 5
// baseline (speedup 1.0000x reference)
#include <cuda_runtime.h>

#define BATCH 128
#define SEQ   2048
#define KDIM  128
#define CAPS  32
#define DCAP  16
#define MCOLS 512
#define NT_R  16          // tiles for k_reduce
#define NTILES 8          // tiles for iteration kernels (2 subtiles each)
#define TILEN 128

#define XS_STRIDE 132
#define PS_STRIDE 36
#define SMEM_FLOATS (TILEN*XS_STRIDE + CAPS*KDIM + TILEN*PS_STRIDE)
#define SMEM_BYTES  (SMEM_FLOATS * 4)

typedef unsigned long long u64;

__device__ __forceinline__ u64 f2dup(float v) {
    u64 r; asm("mov.b64 %0, {%1, %1};" : "=l"(r) : "f"(v)); return r;
}
__device__ __forceinline__ u64 ffma2(u64 a, u64 b, u64 c) {
    u64 d; asm("fma.rn.f32x2 %0, %1, %2, %3;" : "=l"(d) : "l"(a), "l"(b), "l"(c));
    return d;
}
__device__ __forceinline__ u64 fadd2(u64 a, u64 b) {
    u64 d; asm("add.rn.f32x2 %0, %1, %2;" : "=l"(d) : "l"(a), "l"(b)); return d;
}
__device__ __forceinline__ float2 f2unpack(u64 v) {
    float2 f; asm("mov.b64 {%0, %1}, %2;" : "=f"(f.x), "=f"(f.y) : "l"(v)); return f;
}

// ---- scratch ----
__device__ float g_Spart[BATCH][NT_R][KDIM];
__device__ float g_W2[BATCH][CAPS][KDIM];               // k-major
__device__ float g_ypart[BATCH][NTILES][CAPS * KDIM];
__device__ float g_y[BATCH][CAPS * KDIM];

// ============================================================
// Kernel 1: partial column sums of x. grid (NT_R, BATCH), 256 thr.
// ============================================================
__global__ void k_reduce(const float* __restrict__ x) {
    int b = blockIdx.y, p = blockIdx.x, t = threadIdx.x;
    int k4 = t & 31, rr = t >> 5;
    __shared__ float4 red[8][32];
    const float4* xp = (const float4*)(x + ((size_t)(b * SEQ + p * TILEN)) * KDIM);
    float4 s = make_float4(0.f, 0.f, 0.f, 0.f);
#pragma unroll
    for (int j = 0; j < 16; ++j) {
        float4 v = xp[(rr + 8 * j) * 32 + k4];
        s.x += v.x; s.y += v.y; s.z += v.z; s.w += v.w;
    }
    red[rr][k4] = s;
    __syncthreads();
    if (t < 32) {
        float4 a = red[0][t];
#pragma unroll
        for (int r = 1; r < 8; ++r) {
            float4 v = red[r][t];
            a.x += v.x; a.y += v.y; a.z += v.z; a.w += v.w;
        }
        *(float4*)&g_Spart[b][p][t * 4] = a;
    }
}

// ---- W2[b][c][k] = sum_d kernel[k, c*16+d] * o[b,c,d] ----
__device__ __forceinline__ void compute_W2(int b, int t,
                                           const float* os,
                                           const float* __restrict__ w) {
#pragma unroll
    for (int i = 0; i < 8; ++i) {
        int idx = t + i * 512;
        int c = idx >> 7, k = idx & 127;
        const float4* wr = (const float4*)(w + k * MCOLS + c * DCAP);
        const float4* ov = (const float4*)(os + c * DCAP);
        float acc = 0.f;
#pragma unroll
        for (int q = 0; q < 4; ++q) {
            float4 a = wr[q], o4 = ov[q];
            acc += a.x * o4.x + a.y * o4.y + a.z * o4.z + a.w * o4.w;
        }
        g_W2[b][c][k] = acc;
    }
}

// ============================================================
// Kernel 2: o1 = squash((1/32)*S@kernel) + fused W2. grid 128, 512 thr.
// ============================================================
__global__ void k_o_first(const float* __restrict__ w) {
    int b = blockIdx.x, t = threadIdx.x;
    __shared__ float S[KDIM];
    __shared__ float os[MCOLS];
    if (t < KDIM) {
        float s = 0.f;
#pragma unroll
        for (int p = 0; p < NT_R; ++p) s += g_Spart[b][p][t];
        S[t] = s * (1.f / 32.f);
    }
    __syncthreads();
    float acc = 0.f;
#pragma unroll 4
    for (int k = 0; k < KDIM; ++k) acc += S[k] * w[k * MCOLS + t];
    float sq = acc * acc;
#pragma unroll
    for (int off = 8; off >= 1; off >>= 1)
        sq += __shfl_xor_sync(0xffffffffu, sq, off, 16);
    float s2 = sq + 1e-7f;
    float scale = sqrtf(s2) / (0.5f + s2);
    os[t] = scale * acc;
    __syncthreads();
    compute_W2(b, t, os, w);
}

// ============================================================
// Kernel 3: fused routing iteration, 2 subtiles of 128 rows per CTA.
// grid (NTILES, BATCH), 256 threads, 100KB dynamic smem.
// ============================================================
__global__ void __launch_bounds__(256, 2) k_iter(const float* __restrict__ x) {
    extern __shared__ float sm[];
    float* xs  = sm;                             // [TILEN][XS_STRIDE]
    float* w2t = sm + TILEN * XS_STRIDE;         // [CAPS][KDIM]
    float* ps  = w2t + CAPS * KDIM;              // [TILEN][PS_STRIDE]
    u64* buf   = (u64*)xs;                       // epilogue combine (overlays xs)

    int b = blockIdx.y, tile = blockIdx.x, t = threadIdx.x;
    int wid = t >> 5, l = t & 31;

    // W2 once per CTA
    const float* w2g = (const float*)g_W2[b];
#pragma unroll
    for (int i = 0; i < 16; ++i) w2t[t + i * 256] = w2g[t + i * 256];

    // persistent phase-2 accumulators (both subtiles)
    int g2 = wid & 3, nh = wid >> 2;
    int c0p2 = g2 * 8;
    int k0p2 = l * 4;
    u64 acc2[4][4];
#pragma unroll
    for (int p = 0; p < 4; ++p)
#pragma unroll
        for (int kk = 0; kk < 4; ++kk) acc2[p][kk] = 0ull;

    for (int sub = 0; sub < 2; ++sub) {
        __syncthreads();  // prev subtile reads of xs/ps done (and w2t ready)

        // load x subtile
        const float4* xb = (const float4*)(
            x + ((size_t)(b * SEQ + (tile * 2 + sub) * TILEN)) * KDIM);
#pragma unroll
        for (int i = 0; i < 16; ++i) {
            int lin = t + i * 256;
            int row = lin >> 5, c4 = lin & 31;
            float4 v = xb[row * 32 + c4];
            *(float4*)&xs[row * XS_STRIDE + c4 * 4] = v;
        }
        __syncthreads();

        // ---- phase 1: logits[n][c] = sum_k xs[n][k]*w2t[c][k] ----
        // warp: c0=(wid&3)*8 (8 capsules), n-half (wid>>2); 2 rows/thread.
        {
            int c0 = (wid & 3) * 8;
            int n0 = (wid >> 2) * 64 + l;
            u64 acc[2][8];
#pragma unroll
            for (int i = 0; i < 2; ++i)
#pragma unroll
                for (int j = 0; j < 8; ++j) acc[i][j] = 0ull;

            const float* x0 = &xs[n0 * XS_STRIDE];
            const float* x1 = &xs[(n0 + 32) * XS_STRIDE];
#pragma unroll 2
            for (int k = 0; k < KDIM; k += 4) {
                ulonglong2 xa0 = *(const ulonglong2*)&x0[k];
                ulonglong2 xa1 = *(const ulonglong2*)&x1[k];
#pragma unroll
                for (int j = 0; j < 8; ++j) {
                    ulonglong2 wv = *(const ulonglong2*)&w2t[(c0 + j) * KDIM + k];
                    acc[0][j] = ffma2(xa0.x, wv.x, acc[0][j]);
                    acc[0][j] = ffma2(xa0.y, wv.y, acc[0][j]);
                    acc[1][j] = ffma2(xa1.x, wv.x, acc[1][j]);
                    acc[1][j] = ffma2(xa1.y, wv.y, acc[1][j]);
                }
            }
#pragma unroll
            for (int i = 0; i < 2; ++i) {
                int n = n0 + 32 * i;
#pragma unroll
                for (int q = 0; q < 2; ++q) {
                    float2 e0 = f2unpack(acc[i][q * 4 + 0]);
                    float2 e1 = f2unpack(acc[i][q * 4 + 1]);
                    float2 e2 = f2unpack(acc[i][q * 4 + 2]);
                    float2 e3 = f2unpack(acc[i][q * 4 + 3]);
                    *(float4*)&ps[n * PS_STRIDE + c0 + q * 4] =
                        make_float4(e0.x + e0.y, e1.x + e1.y,
                                    e2.x + e2.y, e3.x + e3.y);
                }
            }
        }
        __syncthreads();

        // ---- softmax over capsules (float4, conflict-free) ----
        if (t < TILEN) {
            float4 r[8];
            float* row = &ps[t * PS_STRIDE];
#pragma unroll
            for (int j = 0; j < 8; ++j) r[j] = *(const float4*)&row[j * 4];
            float mx = r[0].x;
#pragma unroll
            for (int j = 0; j < 8; ++j) {
                mx = fmaxf(mx, fmaxf(fmaxf(r[j].x, r[j].y), fmaxf(r[j].z, r[j].w)));
            }
            float sum = 0.f;
#pragma unroll
            for (int j = 0; j < 8; ++j) {
                r[j].x = __expf(r[j].x - mx); r[j].y = __expf(r[j].y - mx);
                r[j].z = __expf(r[j].z - mx); r[j].w = __expf(r[j].w - mx);
                sum += r[j].x + r[j].y + r[j].z + r[j].w;
            }
            float inv = 1.f / sum;
#pragma unroll
            for (int j = 0; j < 8; ++j) {
                r[j].x *= inv; r[j].y *= inv; r[j].z *= inv; r[j].w *= inv;
                *(float4*)&row[j * 4] = r[j];
            }
        }
        __syncthreads();

        // ---- phase 2: accumulate y[c][k] += probs[n][c]*xs[n][k] ----
        {
            int nbase = nh * 64;
#pragma unroll 4
            for (int nn = 0; nn < 64; ++nn) {
                int n = nbase + nn;
                ulonglong2 pv0 = *(const ulonglong2*)&ps[n * PS_STRIDE + c0p2];
                ulonglong2 pv1 = *(const ulonglong2*)&ps[n * PS_STRIDE + c0p2 + 4];
                float4 xa = *(const float4*)&xs[n * XS_STRIDE + k0p2];
                u64 xd0 = f2dup(xa.x), xd1 = f2dup(xa.y);
                u64 xd2 = f2dup(xa.z), xd3 = f2dup(xa.w);
                acc2[0][0] = ffma2(pv0.x, xd0, acc2[0][0]);
                acc2[0][1] = ffma2(pv0.x, xd1, acc2[0][1]);
                acc2[0][2] = ffma2(pv0.x, xd2, acc2[0][2]);
                acc2[0][3] = ffma2(pv0.x, xd3, acc2[0][3]);
                acc2[1][0] = ffma2(pv0.y, xd0, acc2[1][0]);
                acc2[1][1] = ffma2(pv0.y, xd1, acc2[1][1]);
                acc2[1][2] = ffma2(pv0.y, xd2, acc2[1][2]);
                acc2[1][3] = ffma2(pv0.y, xd3, acc2[1][3]);
                acc2[2][0] = ffma2(pv1.x, xd0, acc2[2][0]);
                acc2[2][1] = ffma2(pv1.x, xd1, acc2[2][1]);
                acc2[2][2] = ffma2(pv1.x, xd2, acc2[2][2]);
                acc2[2][3] = ffma2(pv1.x, xd3, acc2[2][3]);
                acc2[3][0] = ffma2(pv1.y, xd0, acc2[3][0]);
                acc2[3][1] = ffma2(pv1.y, xd1, acc2[3][1]);
                acc2[3][2] = ffma2(pv1.y, xd2, acc2[3][2]);
                acc2[3][3] = ffma2(pv1.y, xd3, acc2[3][3]);
            }
        }
    }

    // ---- combine n-halves and write per-tile partial ----
    __syncthreads();               // all xs/ps reads done; buf overlays xs
    if (nh == 1) {
#pragma unroll
        for (int p = 0; p < 4; ++p)
#pragma unroll
            for (int kk = 0; kk < 4; ++kk)
                buf[(p * 4 + kk) * 128 + g2 * 32 + l] = acc2[p][kk];
    }
    __syncthreads();
    if (nh == 0) {
        float* yo = &g_ypart[b][tile][0];
#pragma unroll
        for (int p = 0; p < 4; ++p) {
#pragma unroll
            for (int kk = 0; kk < 4; ++kk)
                acc2[p][kk] = fadd2(acc2[p][kk], buf[(p * 4 + kk) * 128 + g2 * 32 + l]);
            float2 e0 = f2unpack(acc2[p][0]);
            float2 e1 = f2unpack(acc2[p][1]);
            float2 e2 = f2unpack(acc2[p][2]);
            float2 e3 = f2unpack(acc2[p][3]);
            *(float4*)&yo[(c0p2 + 2 * p) * KDIM + k0p2] =
                make_float4(e0.x, e1.x, e2.x, e3.x);
            *(float4*)&yo[(c0p2 + 2 * p + 1) * KDIM + k0p2] =
                make_float4(e0.y, e1.y, e2.y, e3.y);
        }
    }
}

// ============================================================
// Kernel 4: wide reduction of y partials. grid (8, BATCH), 512 thr.
// ============================================================
__global__ void k_yred() {
    int b = blockIdx.y, t = threadIdx.x;
    int idx = blockIdx.x * 512 + t;
    float s = 0.f;
#pragma unroll
    for (int p = 0; p < NTILES; ++p) s += g_ypart[b][p][idx];
    g_y[b][idx] = s;
}

// ============================================================
// Kernel 5: u = y @ kernel, squash; write output or fused W2.
// grid 128, 512 thr.
// ============================================================
__global__ void k_fin(const float* __restrict__ w, float* __restrict__ out) {
    int b = blockIdx.x, t = threadIdx.x;
    __shared__ float ys[CAPS * KDIM];
    __shared__ float os[MCOLS];
#pragma unroll
    for (int i = 0; i < 8; ++i) ys[t + i * 512] = g_y[b][t + i * 512];
    __syncthreads();
    int c = t >> 4;
    const float* yr = &ys[c * KDIM];
    float acc = 0.f;
#pragma unroll 8
    for (int k = 0; k < KDIM; ++k) acc += yr[k] * w[k * MCOLS + t];
    float sq = acc * acc;
#pragma unroll
    for (int off = 8; off >= 1; off >>= 1)
        sq += __shfl_xor_sync(0xffffffffu, sq, off, 16);
    float s2 = sq + 1e-7f;
    float scale = sqrtf(s2) / (0.5f + s2);
    float val = scale * acc;
    if (out) {
        out[b * MCOLS + t] = val;
    } else {
        os[t] = val;
        __syncthreads();
        compute_W2(b, t, os, w);
    }
}

extern "C" void kernel_launch(void* const* d_in, const int* in_sizes, int n_in,
                              void* d_out, int out_size) {
    const float* x = (const float*)d_in[0];
    const float* w = (const float*)d_in[1];
    if (n_in >= 2 && in_sizes[0] == MCOLS * KDIM) {
        x = (const float*)d_in[1];
        w = (const float*)d_in[0];
    }
    (void)out_size;

    cudaFuncSetAttribute(k_iter, cudaFuncAttributeMaxDynamicSharedMemorySize, SMEM_BYTES);

    k_reduce<<<dim3(NT_R, BATCH), 256>>>(x);
    k_o_first<<<BATCH, 512>>>(w);

    for (int r = 0; r < 2; ++r) {
        k_iter<<<dim3(NTILES, BATCH), 256, SMEM_BYTES>>>(x);
        k_yred<<<dim3(8, BATCH), 512>>>();
        k_fin<<<BATCH, 512>>>(w, (r == 1) ? (float*)d_out : nullptr);
    }
}

// round 7
// speedup vs baseline: 1.2800x; 1.2800x over previous
#include <cuda_runtime.h>
#include <cuda_bf16.h>
#include <cstdint>

#define BATCH 128
#define SEQ   2048
#define KDIM  128
#define CAPS  32
#define DCAP  16
#define MCOLS 512
#define NT_R  16
#define NTILES 16
#define TILEN 128

// bf16 tile strides (in u16 elements): 136 -> 272B rows, ldmatrix conflict-free
#define XST 136
// smem byte offsets
#define SM_XH 0
#define SM_XL 34816
#define SM_WH 69632
#define SM_WL 78336
#define SM_PH 87040
#define SM_PL 95744
#define SM_TOTAL 104448

__device__ __forceinline__ uint32_t smem_u32(const void* p) {
    uint32_t a;
    asm("{ .reg .u64 t; cvta.to.shared.u64 t, %1; cvt.u32.u64 %0, t; }"
        : "=r"(a) : "l"(p));
    return a;
}
__device__ __forceinline__ void ldsm_x4(uint32_t a, uint32_t r[4]) {
    asm volatile("ldmatrix.sync.aligned.m8n8.x4.shared.b16 {%0,%1,%2,%3}, [%4];"
        : "=r"(r[0]), "=r"(r[1]), "=r"(r[2]), "=r"(r[3]) : "r"(a));
}
__device__ __forceinline__ void ldsm_x2(uint32_t a, uint32_t r[2]) {
    asm volatile("ldmatrix.sync.aligned.m8n8.x2.shared.b16 {%0,%1}, [%2];"
        : "=r"(r[0]), "=r"(r[1]) : "r"(a));
}
__device__ __forceinline__ void ldsm_x2t(uint32_t a, uint32_t r[2]) {
    asm volatile("ldmatrix.sync.aligned.m8n8.x2.trans.shared.b16 {%0,%1}, [%2];"
        : "=r"(r[0]), "=r"(r[1]) : "r"(a));
}
__device__ __forceinline__ void mma_bf16(float c[4], const uint32_t a[4],
                                         const uint32_t b[2]) {
    asm volatile("mma.sync.aligned.m16n8k16.row.col.f32.bf16.bf16.f32 "
        "{%0,%1,%2,%3}, {%4,%5,%6,%7}, {%8,%9}, {%0,%1,%2,%3};"
        : "+f"(c[0]), "+f"(c[1]), "+f"(c[2]), "+f"(c[3])
        : "r"(a[0]), "r"(a[1]), "r"(a[2]), "r"(a[3]), "r"(b[0]), "r"(b[1]));
}
__device__ __forceinline__ uint32_t pack_bf16(float a, float b) {
    __nv_bfloat16 ha = __float2bfloat16(a), hb = __float2bfloat16(b);
    return (uint32_t)__bfloat16_as_ushort(ha)
         | ((uint32_t)__bfloat16_as_ushort(hb) << 16);
}

// ---- scratch ----
__device__ float g_Spart[BATCH][NT_R][KDIM];
__device__ float g_W2[BATCH][CAPS][KDIM];
__device__ unsigned short g_W2h[BATCH][CAPS * XST];
__device__ unsigned short g_W2l[BATCH][CAPS * XST];
__device__ float g_ypart[BATCH][NTILES][CAPS * KDIM];
__device__ float g_y[BATCH][CAPS * KDIM];

// ============================================================
// Kernel 1: partial column sums of x. grid (NT_R, BATCH), 256 thr.
// ============================================================
__global__ void k_reduce(const float* __restrict__ x) {
    int b = blockIdx.y, p = blockIdx.x, t = threadIdx.x;
    int k4 = t & 31, rr = t >> 5;
    __shared__ float4 red[8][32];
    const float4* xp = (const float4*)(x + ((size_t)(b * SEQ + p * TILEN)) * KDIM);
    float4 s = make_float4(0.f, 0.f, 0.f, 0.f);
#pragma unroll
    for (int j = 0; j < 16; ++j) {
        float4 v = xp[(rr + 8 * j) * 32 + k4];
        s.x += v.x; s.y += v.y; s.z += v.z; s.w += v.w;
    }
    red[rr][k4] = s;
    __syncthreads();
    if (t < 32) {
        float4 a = red[0][t];
#pragma unroll
        for (int r = 1; r < 8; ++r) {
            float4 v = red[r][t];
            a.x += v.x; a.y += v.y; a.z += v.z; a.w += v.w;
        }
        *(float4*)&g_Spart[b][p][t * 4] = a;
    }
}

// ---- W2[b][c][k] = sum_d kernel[k, c*16+d] * o[b,c,d] ----
__device__ __forceinline__ void compute_W2(int b, int t, const float* os,
                                           const float* __restrict__ w) {
#pragma unroll
    for (int i = 0; i < 8; ++i) {
        int idx = t + i * 512;
        int c = idx >> 7, k = idx & 127;
        const float4* wr = (const float4*)(w + k * MCOLS + c * DCAP);
        const float4* ov = (const float4*)(os + c * DCAP);
        float acc = 0.f;
#pragma unroll
        for (int q = 0; q < 4; ++q) {
            float4 a = wr[q], o4 = ov[q];
            acc += a.x * o4.x + a.y * o4.y + a.z * o4.z + a.w * o4.w;
        }
        g_W2[b][c][k] = acc;
    }
}

// ============================================================
// Kernel 2: o1 = squash((1/32)*S@kernel) + fused W2. grid 128, 512 thr.
// ============================================================
__global__ void k_o_first(const float* __restrict__ w) {
    int b = blockIdx.x, t = threadIdx.x;
    __shared__ float S[KDIM];
    __shared__ float os[MCOLS];
    if (t < KDIM) {
        float s = 0.f;
#pragma unroll
        for (int p = 0; p < NT_R; ++p) s += g_Spart[b][p][t];
        S[t] = s * (1.f / 32.f);
    }
    __syncthreads();
    float acc = 0.f;
#pragma unroll 4
    for (int k = 0; k < KDIM; ++k) acc += S[k] * w[k * MCOLS + t];
    float sq = acc * acc;
#pragma unroll
    for (int off = 8; off >= 1; off >>= 1)
        sq += __shfl_xor_sync(0xffffffffu, sq, off, 16);
    float s2 = sq + 1e-7f;
    float scale = sqrtf(s2) / (0.5f + s2);
    os[t] = scale * acc;
    __syncthreads();
    compute_W2(b, t, os, w);
}

// ============================================================
// Kernel 3: split W2 into bf16 hi/lo padded [c][136] tiles. grid 128, 256 thr.
// ============================================================
__global__ void k_w2split() {
    int b = blockIdx.x, t = threadIdx.x;
    unsigned short* oh = g_W2h[b];
    unsigned short* ol = g_W2l[b];
    for (int i = t; i < CAPS * KDIM; i += 256) {
        int c = i >> 7, k = i & 127;
        float v = g_W2[b][c][k];
        __nv_bfloat16 h = __float2bfloat16(v);
        __nv_bfloat16 l = __float2bfloat16(v - __bfloat162float(h));
        oh[c * XST + k] = __bfloat16_as_ushort(h);
        ol[c * XST + k] = __bfloat16_as_ushort(l);
    }
}

// ============================================================
// Kernel 4: tensor-core routing iteration via mma.sync bf16 (split hi/lo).
// grid (NTILES, BATCH), 256 threads (8 warps), ~102KB dynamic smem.
// ============================================================
__global__ void __launch_bounds__(256, 2) k_iter_mma(const float* __restrict__ x) {
    extern __shared__ char sm[];
    uint32_t sb = smem_u32(sm);
    int b = blockIdx.y, tile = blockIdx.x, t = threadIdx.x;
    int wid = t >> 5, l = t & 31;

    // load W2 tiles (8704B each as u32)
    {
        const uint32_t* wh = (const uint32_t*)g_W2h[b];
        const uint32_t* wl = (const uint32_t*)g_W2l[b];
        uint32_t* swh = (uint32_t*)(sm + SM_WH);
        uint32_t* swl = (uint32_t*)(sm + SM_WL);
        for (int i = t; i < CAPS * XST / 2; i += 256) {
            swh[i] = wh[i]; swl[i] = wl[i];
        }
    }

    // load x subtile, split to bf16 hi/lo
    {
        const float4* xb = (const float4*)(x + ((size_t)(b * SEQ + tile * TILEN)) * KDIM);
        uint32_t* xh = (uint32_t*)(sm + SM_XH);
        uint32_t* xl = (uint32_t*)(sm + SM_XL);
#pragma unroll
        for (int i = 0; i < 16; ++i) {
            int lin = t + i * 256;
            int row = lin >> 5, c4 = lin & 31;
            float4 v = xb[row * 32 + c4];
            float hx = __bfloat162float(__float2bfloat16(v.x));
            float hy = __bfloat162float(__float2bfloat16(v.y));
            float hz = __bfloat162float(__float2bfloat16(v.z));
            float hw = __bfloat162float(__float2bfloat16(v.w));
            int u = (row * XST + c4 * 4) >> 1;
            xh[u]     = pack_bf16(v.x, v.y);
            xh[u + 1] = pack_bf16(v.z, v.w);
            xl[u]     = pack_bf16(v.x - hx, v.y - hy);
            xl[u + 1] = pack_bf16(v.z - hz, v.w - hw);
        }
    }
    __syncthreads();

    // ---- phase 1: logits[128n][32c] = X @ W2^T (split bf16, 3 combos) ----
    int m0 = wid * 16;
    float c1[4][4];
#pragma unroll
    for (int j = 0; j < 4; ++j)
#pragma unroll
        for (int e = 0; e < 4; ++e) c1[j][e] = 0.f;

#pragma unroll
    for (int ks = 0; ks < 8; ++ks) {
        int k0 = ks * 16;
        uint32_t aaddr = sb + SM_XH + (uint32_t)(m0 + (l & 15)) * (XST * 2)
                       + k0 * 2 + (l >> 4) * 16;
        uint32_t ah[4], al[4];
        ldsm_x4(aaddr, ah);
        ldsm_x4(aaddr + (SM_XL - SM_XH), al);
#pragma unroll
        for (int j = 0; j < 4; ++j) {
            uint32_t baddr = sb + SM_WH + (uint32_t)(j * 8 + (l & 7)) * (XST * 2)
                           + k0 * 2 + ((l >> 3) & 1) * 16;
            uint32_t bh[2], bl[2];
            ldsm_x2(baddr, bh);
            ldsm_x2(baddr + (SM_WL - SM_WH), bl);
            mma_bf16(c1[j], ah, bh);
            mma_bf16(c1[j], ah, bl);
            mma_bf16(c1[j], al, bh);
        }
    }

    // ---- softmax over 32 capsules per row (fragments + 4-lane shfl) ----
    {
        float mx0 = -1e30f, mx1 = -1e30f;
#pragma unroll
        for (int j = 0; j < 4; ++j) {
            mx0 = fmaxf(mx0, fmaxf(c1[j][0], c1[j][1]));
            mx1 = fmaxf(mx1, fmaxf(c1[j][2], c1[j][3]));
        }
        mx0 = fmaxf(mx0, __shfl_xor_sync(0xffffffffu, mx0, 1));
        mx0 = fmaxf(mx0, __shfl_xor_sync(0xffffffffu, mx0, 2));
        mx1 = fmaxf(mx1, __shfl_xor_sync(0xffffffffu, mx1, 1));
        mx1 = fmaxf(mx1, __shfl_xor_sync(0xffffffffu, mx1, 2));
        float s0 = 0.f, s1 = 0.f;
#pragma unroll
        for (int j = 0; j < 4; ++j) {
            c1[j][0] = __expf(c1[j][0] - mx0); s0 += c1[j][0];
            c1[j][1] = __expf(c1[j][1] - mx0); s0 += c1[j][1];
            c1[j][2] = __expf(c1[j][2] - mx1); s1 += c1[j][2];
            c1[j][3] = __expf(c1[j][3] - mx1); s1 += c1[j][3];
        }
        s0 += __shfl_xor_sync(0xffffffffu, s0, 1);
        s0 += __shfl_xor_sync(0xffffffffu, s0, 2);
        s1 += __shfl_xor_sync(0xffffffffu, s1, 1);
        s1 += __shfl_xor_sync(0xffffffffu, s1, 2);
        float i0 = 1.f / s0, i1 = 1.f / s1;

        unsigned short* ph = (unsigned short*)(sm + SM_PH);
        unsigned short* pl = (unsigned short*)(sm + SM_PL);
        int n = m0 + (l >> 2);
#pragma unroll
        for (int j = 0; j < 4; ++j) {
#pragma unroll
            for (int e = 0; e < 2; ++e) {
                int c = j * 8 + (l & 3) * 2 + e;
                float p0 = c1[j][e] * i0;
                float p1 = c1[j][2 + e] * i1;
                __nv_bfloat16 h0 = __float2bfloat16(p0);
                __nv_bfloat16 h1 = __float2bfloat16(p1);
                ph[c * XST + n]     = __bfloat16_as_ushort(h0);
                ph[c * XST + n + 8] = __bfloat16_as_ushort(h1);
                pl[c * XST + n] =
                    __bfloat16_as_ushort(__float2bfloat16(p0 - __bfloat162float(h0)));
                pl[c * XST + n + 8] =
                    __bfloat16_as_ushort(__float2bfloat16(p1 - __bfloat162float(h1)));
            }
        }
    }
    __syncthreads();

    // ---- phase 2: Y^T[32c][128k] = P^T @ X (contraction over n) ----
    int cw = wid & 1, kw = wid >> 1;
    int m0c = cw * 16;
    float c2[4][4];
#pragma unroll
    for (int j = 0; j < 4; ++j)
#pragma unroll
        for (int e = 0; e < 4; ++e) c2[j][e] = 0.f;

#pragma unroll
    for (int ns = 0; ns < 8; ++ns) {
        int n0 = ns * 16;
        uint32_t aaddr = sb + SM_PH + (uint32_t)(m0c + (l & 15)) * (XST * 2)
                       + n0 * 2 + (l >> 4) * 16;
        uint32_t ah[4], al[4];
        ldsm_x4(aaddr, ah);
        ldsm_x4(aaddr + (SM_PL - SM_PH), al);
#pragma unroll
        for (int j = 0; j < 4; ++j) {
            int k0 = kw * 32 + j * 8;
            uint32_t baddr = sb + SM_XH + (uint32_t)(n0 + (l & 15)) * (XST * 2)
                           + k0 * 2;
            uint32_t bh[2], bl[2];
            ldsm_x2t(baddr, bh);
            ldsm_x2t(baddr + (SM_XL - SM_XH), bl);
            mma_bf16(c2[j], ah, bh);
            mma_bf16(c2[j], ah, bl);
            mma_bf16(c2[j], al, bh);
        }
    }

    // ---- write y partial ----
    {
        float* yo = &g_ypart[b][tile][0];
        int cr = m0c + (l >> 2);
#pragma unroll
        for (int j = 0; j < 4; ++j) {
            int k = kw * 32 + j * 8 + (l & 3) * 2;
            yo[cr * KDIM + k]           = c2[j][0];
            yo[cr * KDIM + k + 1]       = c2[j][1];
            yo[(cr + 8) * KDIM + k]     = c2[j][2];
            yo[(cr + 8) * KDIM + k + 1] = c2[j][3];
        }
    }
}

// ============================================================
// Kernel 5: sum NTILES y partials. grid (8, BATCH), 512 thr.
// ============================================================
__global__ void k_yred() {
    int b = blockIdx.y, t = threadIdx.x;
    int idx = blockIdx.x * 512 + t;
    float s = 0.f;
#pragma unroll
    for (int p = 0; p < NTILES; ++p) s += g_ypart[b][p][idx];
    g_y[b][idx] = s;
}

// ============================================================
// Kernel 6: u = y @ kernel (exact fp32), squash; output or fused W2.
// grid 128, 512 thr.
// ============================================================
__global__ void k_fin(const float* __restrict__ w, float* __restrict__ out) {
    int b = blockIdx.x, t = threadIdx.x;
    __shared__ float ys[CAPS * KDIM];
    __shared__ float os[MCOLS];
#pragma unroll
    for (int i = 0; i < 8; ++i) ys[t + i * 512] = g_y[b][t + i * 512];
    __syncthreads();
    int c = t >> 4;
    const float* yr = &ys[c * KDIM];
    float acc = 0.f;
#pragma unroll 8
    for (int k = 0; k < KDIM; ++k) acc += yr[k] * w[k * MCOLS + t];
    float sq = acc * acc;
#pragma unroll
    for (int off = 8; off >= 1; off >>= 1)
        sq += __shfl_xor_sync(0xffffffffu, sq, off, 16);
    float s2 = sq + 1e-7f;
    float scale = sqrtf(s2) / (0.5f + s2);
    float val = scale * acc;
    if (out) {
        out[b * MCOLS + t] = val;
    } else {
        os[t] = val;
        __syncthreads();
        compute_W2(b, t, os, w);
    }
}

extern "C" void kernel_launch(void* const* d_in, const int* in_sizes, int n_in,
                              void* d_out, int out_size) {
    const float* x = (const float*)d_in[0];
    const float* w = (const float*)d_in[1];
    if (n_in >= 2 && in_sizes[0] == MCOLS * KDIM) {
        x = (const float*)d_in[1];
        w = (const float*)d_in[0];
    }
    (void)out_size;

    cudaFuncSetAttribute(k_iter_mma, cudaFuncAttributeMaxDynamicSharedMemorySize,
                         SM_TOTAL);

    k_reduce<<<dim3(NT_R, BATCH), 256>>>(x);
    k_o_first<<<BATCH, 512>>>(w);

    for (int r = 0; r < 2; ++r) {
        k_w2split<<<BATCH, 256>>>();
        k_iter_mma<<<dim3(NTILES, BATCH), 256, SM_TOTAL>>>(x);
        k_yred<<<dim3(8, BATCH), 512>>>();
        k_fin<<<BATCH, 512>>>(w, (r == 1) ? (float*)d_out : nullptr);
    }
}

// round 8
// speedup vs baseline: 1.4770x; 1.1539x over previous
#include <cuda_runtime.h>
#include <cuda_bf16.h>
#include <cstdint>

#define BATCH 128
#define SEQ   2048
#define KDIM  128
#define CAPS  32
#define DCAP  16
#define MCOLS 512
#define NT_R  16
#define NTILES 8          // iteration tiles (2 subtiles of 128 each)
#define TILEN 128

// bf16 tile strides (u16 elements): 136 -> 272B rows, ldmatrix conflict-free
#define XST 136
// smem byte offsets
#define SM_XH 0
#define SM_XL 34816
#define SM_WH 69632
#define SM_WL 78336
#define SM_PH 87040
#define SM_PL 95744
#define SM_TOTAL 104448

__device__ __forceinline__ uint32_t smem_u32(const void* p) {
    uint32_t a;
    asm("{ .reg .u64 t; cvta.to.shared.u64 t, %1; cvt.u32.u64 %0, t; }"
        : "=r"(a) : "l"(p));
    return a;
}
__device__ __forceinline__ void ldsm_x4(uint32_t a, uint32_t r[4]) {
    asm volatile("ldmatrix.sync.aligned.m8n8.x4.shared.b16 {%0,%1,%2,%3}, [%4];"
        : "=r"(r[0]), "=r"(r[1]), "=r"(r[2]), "=r"(r[3]) : "r"(a));
}
__device__ __forceinline__ void ldsm_x4t(uint32_t a, uint32_t r[4]) {
    asm volatile("ldmatrix.sync.aligned.m8n8.x4.trans.shared.b16 {%0,%1,%2,%3}, [%4];"
        : "=r"(r[0]), "=r"(r[1]), "=r"(r[2]), "=r"(r[3]) : "r"(a));
}
__device__ __forceinline__ void mma_bf16(float c[4], const uint32_t a[4],
                                         uint32_t b0, uint32_t b1) {
    asm volatile("mma.sync.aligned.m16n8k16.row.col.f32.bf16.bf16.f32 "
        "{%0,%1,%2,%3}, {%4,%5,%6,%7}, {%8,%9}, {%0,%1,%2,%3};"
        : "+f"(c[0]), "+f"(c[1]), "+f"(c[2]), "+f"(c[3])
        : "r"(a[0]), "r"(a[1]), "r"(a[2]), "r"(a[3]), "r"(b0), "r"(b1));
}
__device__ __forceinline__ uint32_t pack_bf16(float a, float b) {
    __nv_bfloat16 ha = __float2bfloat16(a), hb = __float2bfloat16(b);
    return (uint32_t)__bfloat16_as_ushort(ha)
         | ((uint32_t)__bfloat16_as_ushort(hb) << 16);
}

// ---- scratch ----
__device__ float g_Spart[BATCH][NT_R][KDIM];
__device__ float g_W2[BATCH][CAPS][KDIM];
__device__ unsigned short g_W2h[BATCH][CAPS * XST];
__device__ unsigned short g_W2l[BATCH][CAPS * XST];
__device__ float g_ypart[BATCH][NTILES][CAPS * KDIM];
__device__ float g_y[BATCH][CAPS * KDIM];

// ============================================================
// Kernel 1: partial column sums of x. grid (NT_R, BATCH), 256 thr.
// ============================================================
__global__ void k_reduce(const float* __restrict__ x) {
    int b = blockIdx.y, p = blockIdx.x, t = threadIdx.x;
    int k4 = t & 31, rr = t >> 5;
    __shared__ float4 red[8][32];
    const float4* xp = (const float4*)(x + ((size_t)(b * SEQ + p * TILEN)) * KDIM);
    float4 s = make_float4(0.f, 0.f, 0.f, 0.f);
#pragma unroll
    for (int j = 0; j < 16; ++j) {
        float4 v = xp[(rr + 8 * j) * 32 + k4];
        s.x += v.x; s.y += v.y; s.z += v.z; s.w += v.w;
    }
    red[rr][k4] = s;
    __syncthreads();
    if (t < 32) {
        float4 a = red[0][t];
#pragma unroll
        for (int r = 1; r < 8; ++r) {
            float4 v = red[r][t];
            a.x += v.x; a.y += v.y; a.z += v.z; a.w += v.w;
        }
        *(float4*)&g_Spart[b][p][t * 4] = a;
    }
}

// ---- W2[b][c][k] = sum_d kernel[k, c*16+d] * o[b,c,d]; also bf16 hi/lo split ----
__device__ __forceinline__ void compute_W2(int b, int t, const float* os,
                                           const float* __restrict__ w) {
#pragma unroll
    for (int i = 0; i < 8; ++i) {
        int idx = t + i * 512;
        int c = idx >> 7, k = idx & 127;
        const float4* wr = (const float4*)(w + k * MCOLS + c * DCAP);
        const float4* ov = (const float4*)(os + c * DCAP);
        float acc = 0.f;
#pragma unroll
        for (int q = 0; q < 4; ++q) {
            float4 a = wr[q], o4 = ov[q];
            acc += a.x * o4.x + a.y * o4.y + a.z * o4.z + a.w * o4.w;
        }
        g_W2[b][c][k] = acc;
        __nv_bfloat16 h = __float2bfloat16(acc);
        __nv_bfloat16 l = __float2bfloat16(acc - __bfloat162float(h));
        g_W2h[b][c * XST + k] = __bfloat16_as_ushort(h);
        g_W2l[b][c * XST + k] = __bfloat16_as_ushort(l);
    }
}

// ============================================================
// Kernel 2: o1 = squash((1/32)*S@kernel) + fused W2+split. grid 128, 512 thr.
// ============================================================
__global__ void k_o_first(const float* __restrict__ w) {
    int b = blockIdx.x, t = threadIdx.x;
    __shared__ float S[KDIM];
    __shared__ float os[MCOLS];
    if (t < KDIM) {
        float s = 0.f;
#pragma unroll
        for (int p = 0; p < NT_R; ++p) s += g_Spart[b][p][t];
        S[t] = s * (1.f / 32.f);
    }
    __syncthreads();
    float acc = 0.f;
#pragma unroll 4
    for (int k = 0; k < KDIM; ++k) acc += S[k] * w[k * MCOLS + t];
    float sq = acc * acc;
#pragma unroll
    for (int off = 8; off >= 1; off >>= 1)
        sq += __shfl_xor_sync(0xffffffffu, sq, off, 16);
    float s2 = sq + 1e-7f;
    float scale = sqrtf(s2) / (0.5f + s2);
    os[t] = scale * acc;
    __syncthreads();
    compute_W2(b, t, os, w);
}

// ============================================================
// Kernel 3: tensor-core routing iteration (mma.sync bf16 split hi/lo).
// grid (NTILES, BATCH), 256 thr, 2 subtiles of 128 rows per CTA.
// ============================================================
__global__ void __launch_bounds__(256, 2) k_iter_mma(const float* __restrict__ x) {
    extern __shared__ char sm[];
    uint32_t sb = smem_u32(sm);
    int b = blockIdx.y, tile = blockIdx.x, t = threadIdx.x;
    int wid = t >> 5, l = t & 31;

    // load W2 tiles (8704B each as u32)
    {
        const uint32_t* wh = (const uint32_t*)g_W2h[b];
        const uint32_t* wl = (const uint32_t*)g_W2l[b];
        uint32_t* swh = (uint32_t*)(sm + SM_WH);
        uint32_t* swl = (uint32_t*)(sm + SM_WL);
        for (int i = t; i < CAPS * XST / 2; i += 256) {
            swh[i] = wh[i]; swl[i] = wl[i];
        }
    }

    // phase-2 persistent accumulators
    int cw = wid & 1, kw = wid >> 1;
    int m0c = cw * 16;
    float c2[4][4];
#pragma unroll
    for (int j = 0; j < 4; ++j)
#pragma unroll
        for (int e = 0; e < 4; ++e) c2[j][e] = 0.f;

    int m0 = wid * 16;

    for (int sub = 0; sub < 2; ++sub) {
        __syncthreads();   // prev subtile phase-2 reads done; W ready (first pass)

        // ---- load x subtile, split to bf16 hi/lo ----
        {
            const float4* xb = (const float4*)(
                x + ((size_t)(b * SEQ + (tile * 2 + sub) * TILEN)) * KDIM);
            uint32_t* xh = (uint32_t*)(sm + SM_XH);
            uint32_t* xl = (uint32_t*)(sm + SM_XL);
#pragma unroll
            for (int i = 0; i < 16; ++i) {
                int lin = t + i * 256;
                int row = lin >> 5, c4 = lin & 31;
                float4 v = xb[row * 32 + c4];
                float hx = __bfloat162float(__float2bfloat16(v.x));
                float hy = __bfloat162float(__float2bfloat16(v.y));
                float hz = __bfloat162float(__float2bfloat16(v.z));
                float hw = __bfloat162float(__float2bfloat16(v.w));
                int u = (row * XST + c4 * 4) >> 1;
                xh[u]     = pack_bf16(v.x, v.y);
                xh[u + 1] = pack_bf16(v.z, v.w);
                xl[u]     = pack_bf16(v.x - hx, v.y - hy);
                xl[u + 1] = pack_bf16(v.z - hz, v.w - hw);
            }
        }
        __syncthreads();

        // ---- phase 1: logits[128n][32c] = X @ W2^T (3 combos) ----
        float c1[4][4];
#pragma unroll
        for (int j = 0; j < 4; ++j)
#pragma unroll
            for (int e = 0; e < 4; ++e) c1[j][e] = 0.f;

#pragma unroll
        for (int ks = 0; ks < 8; ++ks) {
            int k0 = ks * 16;
            uint32_t aaddr = sb + SM_XH + (uint32_t)(m0 + (l & 15)) * (XST * 2)
                           + k0 * 2 + (l >> 4) * 16;
            uint32_t ah[4], al[4];
            ldsm_x4(aaddr, ah);
            ldsm_x4(aaddr + (SM_XL - SM_XH), al);
#pragma unroll
            for (int p = 0; p < 2; ++p) {
                // x4 B load covers c-groups j=2p and j=2p+1
                uint32_t baddr = sb + SM_WH
                    + (uint32_t)(p * 16 + (l >> 4) * 8 + (l & 7)) * (XST * 2)
                    + k0 * 2 + ((l >> 3) & 1) * 16;
                uint32_t bh[4], bl[4];
                ldsm_x4(baddr, bh);
                ldsm_x4(baddr + (SM_WL - SM_WH), bl);
                mma_bf16(c1[2 * p],     ah, bh[0], bh[1]);
                mma_bf16(c1[2 * p],     ah, bl[0], bl[1]);
                mma_bf16(c1[2 * p],     al, bh[0], bh[1]);
                mma_bf16(c1[2 * p + 1], ah, bh[2], bh[3]);
                mma_bf16(c1[2 * p + 1], ah, bl[2], bl[3]);
                mma_bf16(c1[2 * p + 1], al, bh[2], bh[3]);
            }
        }

        // ---- softmax over 32 capsules per row; write P^T hi/lo ----
        {
            float mx0 = -1e30f, mx1 = -1e30f;
#pragma unroll
            for (int j = 0; j < 4; ++j) {
                mx0 = fmaxf(mx0, fmaxf(c1[j][0], c1[j][1]));
                mx1 = fmaxf(mx1, fmaxf(c1[j][2], c1[j][3]));
            }
            mx0 = fmaxf(mx0, __shfl_xor_sync(0xffffffffu, mx0, 1));
            mx0 = fmaxf(mx0, __shfl_xor_sync(0xffffffffu, mx0, 2));
            mx1 = fmaxf(mx1, __shfl_xor_sync(0xffffffffu, mx1, 1));
            mx1 = fmaxf(mx1, __shfl_xor_sync(0xffffffffu, mx1, 2));
            float s0 = 0.f, s1 = 0.f;
#pragma unroll
            for (int j = 0; j < 4; ++j) {
                c1[j][0] = __expf(c1[j][0] - mx0); s0 += c1[j][0];
                c1[j][1] = __expf(c1[j][1] - mx0); s0 += c1[j][1];
                c1[j][2] = __expf(c1[j][2] - mx1); s1 += c1[j][2];
                c1[j][3] = __expf(c1[j][3] - mx1); s1 += c1[j][3];
            }
            s0 += __shfl_xor_sync(0xffffffffu, s0, 1);
            s0 += __shfl_xor_sync(0xffffffffu, s0, 2);
            s1 += __shfl_xor_sync(0xffffffffu, s1, 1);
            s1 += __shfl_xor_sync(0xffffffffu, s1, 2);
            float i0 = 1.f / s0, i1 = 1.f / s1;

            unsigned short* ph = (unsigned short*)(sm + SM_PH);
            unsigned short* pl = (unsigned short*)(sm + SM_PL);
            int n = m0 + (l >> 2);
#pragma unroll
            for (int j = 0; j < 4; ++j) {
#pragma unroll
                for (int e = 0; e < 2; ++e) {
                    int c = j * 8 + (l & 3) * 2 + e;
                    float p0 = c1[j][e] * i0;
                    float p1 = c1[j][2 + e] * i1;
                    __nv_bfloat16 h0 = __float2bfloat16(p0);
                    __nv_bfloat16 h1 = __float2bfloat16(p1);
                    ph[c * XST + n]     = __bfloat16_as_ushort(h0);
                    ph[c * XST + n + 8] = __bfloat16_as_ushort(h1);
                    pl[c * XST + n] = __bfloat16_as_ushort(
                        __float2bfloat16(p0 - __bfloat162float(h0)));
                    pl[c * XST + n + 8] = __bfloat16_as_ushort(
                        __float2bfloat16(p1 - __bfloat162float(h1)));
                }
            }
        }
        __syncthreads();

        // ---- phase 2: Y^T[32c][128k] += P^T @ X ----
#pragma unroll
        for (int ns = 0; ns < 8; ++ns) {
            int n0 = ns * 16;
            uint32_t aaddr = sb + SM_PH + (uint32_t)(m0c + (l & 15)) * (XST * 2)
                           + n0 * 2 + (l >> 4) * 16;
            uint32_t ah[4], al[4];
            ldsm_x4(aaddr, ah);
            ldsm_x4(aaddr + (SM_PL - SM_PH), al);
#pragma unroll
            for (int p = 0; p < 2; ++p) {
                // x4 trans B load covers k-groups j=2p, j=2p+1
                int k0 = kw * 32 + p * 16;
                uint32_t baddr = sb + SM_XH + (uint32_t)(n0 + (l & 15)) * (XST * 2)
                               + (k0 + 8 * (l >> 4)) * 2;
                uint32_t bh[4], bl[4];
                ldsm_x4t(baddr, bh);
                ldsm_x4t(baddr + (SM_XL - SM_XH), bl);
                mma_bf16(c2[2 * p],     ah, bh[0], bh[1]);
                mma_bf16(c2[2 * p],     ah, bl[0], bl[1]);
                mma_bf16(c2[2 * p],     al, bh[0], bh[1]);
                mma_bf16(c2[2 * p + 1], ah, bh[2], bh[3]);
                mma_bf16(c2[2 * p + 1], ah, bl[2], bl[3]);
                mma_bf16(c2[2 * p + 1], al, bh[2], bh[3]);
            }
        }
    }

    // ---- write y partial ----
    {
        float* yo = &g_ypart[b][tile][0];
        int cr = m0c + (l >> 2);
#pragma unroll
        for (int j = 0; j < 4; ++j) {
            int k = kw * 32 + j * 8 + (l & 3) * 2;
            yo[cr * KDIM + k]           = c2[j][0];
            yo[cr * KDIM + k + 1]       = c2[j][1];
            yo[(cr + 8) * KDIM + k]     = c2[j][2];
            yo[(cr + 8) * KDIM + k + 1] = c2[j][3];
        }
    }
}

// ============================================================
// Kernel 4: sum NTILES y partials (float4). grid (2, BATCH), 512 thr.
// ============================================================
__global__ void k_yred() {
    int b = blockIdx.y, t = threadIdx.x;
    int i4 = blockIdx.x * 512 + t;
    float4 s = make_float4(0.f, 0.f, 0.f, 0.f);
#pragma unroll
    for (int p = 0; p < NTILES; ++p) {
        float4 v = ((const float4*)g_ypart[b][p])[i4];
        s.x += v.x; s.y += v.y; s.z += v.z; s.w += v.w;
    }
    ((float4*)g_y[b])[i4] = s;
}

// ============================================================
// Kernel 5: u = y @ kernel (exact fp32), squash; output or fused W2+split.
// grid 128, 512 thr.
// ============================================================
__global__ void k_fin(const float* __restrict__ w, float* __restrict__ out) {
    int b = blockIdx.x, t = threadIdx.x;
    __shared__ float ys[CAPS * KDIM];
    __shared__ float os[MCOLS];
#pragma unroll
    for (int i = 0; i < 8; ++i) ys[t + i * 512] = g_y[b][t + i * 512];
    __syncthreads();
    int c = t >> 4;
    const float* yr = &ys[c * KDIM];
    float acc = 0.f;
#pragma unroll 8
    for (int k = 0; k < KDIM; ++k) acc += yr[k] * w[k * MCOLS + t];
    float sq = acc * acc;
#pragma unroll
    for (int off = 8; off >= 1; off >>= 1)
        sq += __shfl_xor_sync(0xffffffffu, sq, off, 16);
    float s2 = sq + 1e-7f;
    float scale = sqrtf(s2) / (0.5f + s2);
    float val = scale * acc;
    if (out) {
        out[b * MCOLS + t] = val;
    } else {
        os[t] = val;
        __syncthreads();
        compute_W2(b, t, os, w);
    }
}

extern "C" void kernel_launch(void* const* d_in, const int* in_sizes, int n_in,
                              void* d_out, int out_size) {
    const float* x = (const float*)d_in[0];
    const float* w = (const float*)d_in[1];
    if (n_in >= 2 && in_sizes[0] == MCOLS * KDIM) {
        x = (const float*)d_in[1];
        w = (const float*)d_in[0];
    }
    (void)out_size;

    cudaFuncSetAttribute(k_iter_mma, cudaFuncAttributeMaxDynamicSharedMemorySize,
                         SM_TOTAL);

    k_reduce<<<dim3(NT_R, BATCH), 256>>>(x);
    k_o_first<<<BATCH, 512>>>(w);

    for (int r = 0; r < 2; ++r) {
        k_iter_mma<<<dim3(NTILES, BATCH), 256, SM_TOTAL>>>(x);
        k_yred<<<dim3(2, BATCH), 512>>>();
        k_fin<<<BATCH, 512>>>(w, (r == 1) ? (float*)d_out : nullptr);
    }
}

// round 9
// speedup vs baseline: 1.4797x; 1.0019x over previous
#include <cuda_runtime.h>
#include <cuda_bf16.h>
#include <cstdint>

#define BATCH 128
#define SEQ   2048
#define KDIM  128
#define CAPS  32
#define DCAP  16
#define MCOLS 512
#define NT_R  16
#define NTILES 8          // iteration tiles (2 subtiles of 128 each)
#define TILEN 128

// bf16 tile strides (u16 elements): 136 -> 272B rows, ldmatrix conflict-free
#define XST 136
// smem byte offsets
#define SM_XH 0
#define SM_XL 34816
#define SM_WH 69632
#define SM_WL 78336
#define SM_PH 87040
#define SM_PL 95744
#define SM_TOTAL 104448

__device__ __forceinline__ uint32_t smem_u32(const void* p) {
    uint32_t a;
    asm("{ .reg .u64 t; cvta.to.shared.u64 t, %1; cvt.u32.u64 %0, t; }"
        : "=r"(a) : "l"(p));
    return a;
}
__device__ __forceinline__ void ldsm_x4(uint32_t a, uint32_t r[4]) {
    asm volatile("ldmatrix.sync.aligned.m8n8.x4.shared.b16 {%0,%1,%2,%3}, [%4];"
        : "=r"(r[0]), "=r"(r[1]), "=r"(r[2]), "=r"(r[3]) : "r"(a));
}
__device__ __forceinline__ void ldsm_x4t(uint32_t a, uint32_t r[4]) {
    asm volatile("ldmatrix.sync.aligned.m8n8.x4.trans.shared.b16 {%0,%1,%2,%3}, [%4];"
        : "=r"(r[0]), "=r"(r[1]), "=r"(r[2]), "=r"(r[3]) : "r"(a));
}
__device__ __forceinline__ void mma_bf16(float c[4], const uint32_t a[4],
                                         uint32_t b0, uint32_t b1) {
    asm volatile("mma.sync.aligned.m16n8k16.row.col.f32.bf16.bf16.f32 "
        "{%0,%1,%2,%3}, {%4,%5,%6,%7}, {%8,%9}, {%0,%1,%2,%3};"
        : "+f"(c[0]), "+f"(c[1]), "+f"(c[2]), "+f"(c[3])
        : "r"(a[0]), "r"(a[1]), "r"(a[2]), "r"(a[3]), "r"(b0), "r"(b1));
}
__device__ __forceinline__ uint32_t pack_bf16(float a, float b) {
    __nv_bfloat16 ha = __float2bfloat16(a), hb = __float2bfloat16(b);
    return (uint32_t)__bfloat16_as_ushort(ha)
         | ((uint32_t)__bfloat16_as_ushort(hb) << 16);
}

// ---- scratch ----
__device__ float g_Spart[BATCH][NT_R][KDIM];
__device__ float g_W2[BATCH][CAPS][KDIM];
__device__ unsigned short g_W2h[BATCH][CAPS * XST];
__device__ unsigned short g_W2l[BATCH][CAPS * XST];
__device__ float g_ypart[BATCH][NTILES][CAPS * KDIM];
__device__ float g_y[BATCH][CAPS * KDIM];

// ============================================================
// Kernel 1: partial column sums of x. grid (NT_R, BATCH), 256 thr.
// ============================================================
__global__ void k_reduce(const float* __restrict__ x) {
    int b = blockIdx.y, p = blockIdx.x, t = threadIdx.x;
    int k4 = t & 31, rr = t >> 5;
    __shared__ float4 red[8][32];
    const float4* xp = (const float4*)(x + ((size_t)(b * SEQ + p * TILEN)) * KDIM);
    float4 s = make_float4(0.f, 0.f, 0.f, 0.f);
#pragma unroll
    for (int j = 0; j < 16; ++j) {
        float4 v = xp[(rr + 8 * j) * 32 + k4];
        s.x += v.x; s.y += v.y; s.z += v.z; s.w += v.w;
    }
    red[rr][k4] = s;
    __syncthreads();
    if (t < 32) {
        float4 a = red[0][t];
#pragma unroll
        for (int r = 1; r < 8; ++r) {
            float4 v = red[r][t];
            a.x += v.x; a.y += v.y; a.z += v.z; a.w += v.w;
        }
        *(float4*)&g_Spart[b][p][t * 4] = a;
    }
}

// ---- W2[b][c][k] = sum_d kernel[k, c*16+d] * o[b,c,d]; also bf16 hi/lo split ----
__device__ __forceinline__ void compute_W2(int b, int t, const float* os,
                                           const float* __restrict__ w) {
#pragma unroll
    for (int i = 0; i < 8; ++i) {
        int idx = t + i * 512;
        int c = idx >> 7, k = idx & 127;
        const float4* wr = (const float4*)(w + k * MCOLS + c * DCAP);
        const float4* ov = (const float4*)(os + c * DCAP);
        float acc = 0.f;
#pragma unroll
        for (int q = 0; q < 4; ++q) {
            float4 a = wr[q], o4 = ov[q];
            acc += a.x * o4.x + a.y * o4.y + a.z * o4.z + a.w * o4.w;
        }
        g_W2[b][c][k] = acc;
        __nv_bfloat16 h = __float2bfloat16(acc);
        __nv_bfloat16 l = __float2bfloat16(acc - __bfloat162float(h));
        g_W2h[b][c * XST + k] = __bfloat16_as_ushort(h);
        g_W2l[b][c * XST + k] = __bfloat16_as_ushort(l);
    }
}

// ============================================================
// Kernel 2: o1 = squash((1/32)*S@kernel) + fused W2+split. grid 128, 512 thr.
// ============================================================
__global__ void k_o_first(const float* __restrict__ w) {
    int b = blockIdx.x, t = threadIdx.x;
    __shared__ float S[KDIM];
    __shared__ float os[MCOLS];
    if (t < KDIM) {
        float s = 0.f;
#pragma unroll
        for (int p = 0; p < NT_R; ++p) s += g_Spart[b][p][t];
        S[t] = s * (1.f / 32.f);
    }
    __syncthreads();
    float acc = 0.f;
#pragma unroll 4
    for (int k = 0; k < KDIM; ++k) acc += S[k] * w[k * MCOLS + t];
    float sq = acc * acc;
#pragma unroll
    for (int off = 8; off >= 1; off >>= 1)
        sq += __shfl_xor_sync(0xffffffffu, sq, off, 16);
    float s2 = sq + 1e-7f;
    float scale = sqrtf(s2) / (0.5f + s2);
    os[t] = scale * acc;
    __syncthreads();
    compute_W2(b, t, os, w);
}

// ============================================================
// Kernel 3: tensor-core routing iteration (mma.sync bf16 split hi/lo),
// combo-major mma issue + separate lh accumulator bank (RAW-chain break).
// grid (NTILES, BATCH), 256 thr, 2 subtiles of 128 rows per CTA.
// ============================================================
__global__ void __launch_bounds__(256, 2) k_iter_mma(const float* __restrict__ x) {
    extern __shared__ char sm[];
    uint32_t sb = smem_u32(sm);
    int b = blockIdx.y, tile = blockIdx.x, t = threadIdx.x;
    int wid = t >> 5, l = t & 31;

    // load W2 tiles (8704B each as u32)
    {
        const uint32_t* wh = (const uint32_t*)g_W2h[b];
        const uint32_t* wl = (const uint32_t*)g_W2l[b];
        uint32_t* swh = (uint32_t*)(sm + SM_WH);
        uint32_t* swl = (uint32_t*)(sm + SM_WL);
        for (int i = t; i < CAPS * XST / 2; i += 256) {
            swh[i] = wh[i]; swl[i] = wl[i];
        }
    }

    // phase-2 persistent accumulators (main + lh bank)
    int cw = wid & 1, kw = wid >> 1;
    int m0c = cw * 16;
    float c2[4][4], c2b[4][4];
#pragma unroll
    for (int j = 0; j < 4; ++j)
#pragma unroll
        for (int e = 0; e < 4; ++e) { c2[j][e] = 0.f; c2b[j][e] = 0.f; }

    int m0 = wid * 16;

    for (int sub = 0; sub < 2; ++sub) {
        __syncthreads();   // prev subtile phase-2 reads done; W ready (first pass)

        // ---- load x subtile, split to bf16 hi/lo ----
        {
            const float4* xb = (const float4*)(
                x + ((size_t)(b * SEQ + (tile * 2 + sub) * TILEN)) * KDIM);
            uint32_t* xh = (uint32_t*)(sm + SM_XH);
            uint32_t* xl = (uint32_t*)(sm + SM_XL);
#pragma unroll
            for (int i = 0; i < 16; ++i) {
                int lin = t + i * 256;
                int row = lin >> 5, c4 = lin & 31;
                float4 v = xb[row * 32 + c4];
                float hx = __bfloat162float(__float2bfloat16(v.x));
                float hy = __bfloat162float(__float2bfloat16(v.y));
                float hz = __bfloat162float(__float2bfloat16(v.z));
                float hw = __bfloat162float(__float2bfloat16(v.w));
                int u = (row * XST + c4 * 4) >> 1;
                xh[u]     = pack_bf16(v.x, v.y);
                xh[u + 1] = pack_bf16(v.z, v.w);
                xl[u]     = pack_bf16(v.x - hx, v.y - hy);
                xl[u + 1] = pack_bf16(v.z - hz, v.w - hw);
            }
        }
        __syncthreads();

        // ---- phase 1: logits[128n][32c] = X @ W2^T, combo-major issue ----
        float c1[4][4], c1b[4][4];
#pragma unroll
        for (int j = 0; j < 4; ++j)
#pragma unroll
            for (int e = 0; e < 4; ++e) { c1[j][e] = 0.f; c1b[j][e] = 0.f; }

#pragma unroll
        for (int ks = 0; ks < 8; ++ks) {
            int k0 = ks * 16;
            uint32_t aaddr = sb + SM_XH + (uint32_t)(m0 + (l & 15)) * (XST * 2)
                           + k0 * 2 + (l >> 4) * 16;
            uint32_t ah[4], al[4];
            ldsm_x4(aaddr, ah);
            ldsm_x4(aaddr + (SM_XL - SM_XH), al);
            uint32_t b0addr = sb + SM_WH
                + (uint32_t)((l >> 4) * 8 + (l & 7)) * (XST * 2)
                + k0 * 2 + ((l >> 3) & 1) * 16;
            uint32_t b1addr = b0addr + 16 * (XST * 2);
            uint32_t bh0[4], bl0[4], bh1[4], bl1[4];
            ldsm_x4(b0addr, bh0);
            ldsm_x4(b0addr + (SM_WL - SM_WH), bl0);
            ldsm_x4(b1addr, bh1);
            ldsm_x4(b1addr + (SM_WL - SM_WH), bl1);
            // hh burst (4 independent accums)
            mma_bf16(c1[0], ah, bh0[0], bh0[1]);
            mma_bf16(c1[1], ah, bh0[2], bh0[3]);
            mma_bf16(c1[2], ah, bh1[0], bh1[1]);
            mma_bf16(c1[3], ah, bh1[2], bh1[3]);
            // hl burst
            mma_bf16(c1[0], ah, bl0[0], bl0[1]);
            mma_bf16(c1[1], ah, bl0[2], bl0[3]);
            mma_bf16(c1[2], ah, bl1[0], bl1[1]);
            mma_bf16(c1[3], ah, bl1[2], bl1[3]);
            // lh burst -> separate bank
            mma_bf16(c1b[0], al, bh0[0], bh0[1]);
            mma_bf16(c1b[1], al, bh0[2], bh0[3]);
            mma_bf16(c1b[2], al, bh1[0], bh1[1]);
            mma_bf16(c1b[3], al, bh1[2], bh1[3]);
        }
#pragma unroll
        for (int j = 0; j < 4; ++j)
#pragma unroll
            for (int e = 0; e < 4; ++e) c1[j][e] += c1b[j][e];

        // ---- softmax over 32 capsules per row; write P^T hi/lo ----
        {
            float mx0 = -1e30f, mx1 = -1e30f;
#pragma unroll
            for (int j = 0; j < 4; ++j) {
                mx0 = fmaxf(mx0, fmaxf(c1[j][0], c1[j][1]));
                mx1 = fmaxf(mx1, fmaxf(c1[j][2], c1[j][3]));
            }
            mx0 = fmaxf(mx0, __shfl_xor_sync(0xffffffffu, mx0, 1));
            mx0 = fmaxf(mx0, __shfl_xor_sync(0xffffffffu, mx0, 2));
            mx1 = fmaxf(mx1, __shfl_xor_sync(0xffffffffu, mx1, 1));
            mx1 = fmaxf(mx1, __shfl_xor_sync(0xffffffffu, mx1, 2));
            float s0 = 0.f, s1 = 0.f;
#pragma unroll
            for (int j = 0; j < 4; ++j) {
                c1[j][0] = __expf(c1[j][0] - mx0); s0 += c1[j][0];
                c1[j][1] = __expf(c1[j][1] - mx0); s0 += c1[j][1];
                c1[j][2] = __expf(c1[j][2] - mx1); s1 += c1[j][2];
                c1[j][3] = __expf(c1[j][3] - mx1); s1 += c1[j][3];
            }
            s0 += __shfl_xor_sync(0xffffffffu, s0, 1);
            s0 += __shfl_xor_sync(0xffffffffu, s0, 2);
            s1 += __shfl_xor_sync(0xffffffffu, s1, 1);
            s1 += __shfl_xor_sync(0xffffffffu, s1, 2);
            float i0 = 1.f / s0, i1 = 1.f / s1;

            unsigned short* ph = (unsigned short*)(sm + SM_PH);
            unsigned short* pl = (unsigned short*)(sm + SM_PL);
            int n = m0 + (l >> 2);
#pragma unroll
            for (int j = 0; j < 4; ++j) {
#pragma unroll
                for (int e = 0; e < 2; ++e) {
                    int c = j * 8 + (l & 3) * 2 + e;
                    float p0 = c1[j][e] * i0;
                    float p1 = c1[j][2 + e] * i1;
                    __nv_bfloat16 h0 = __float2bfloat16(p0);
                    __nv_bfloat16 h1 = __float2bfloat16(p1);
                    ph[c * XST + n]     = __bfloat16_as_ushort(h0);
                    ph[c * XST + n + 8] = __bfloat16_as_ushort(h1);
                    pl[c * XST + n] = __bfloat16_as_ushort(
                        __float2bfloat16(p0 - __bfloat162float(h0)));
                    pl[c * XST + n + 8] = __bfloat16_as_ushort(
                        __float2bfloat16(p1 - __bfloat162float(h1)));
                }
            }
        }
        __syncthreads();

        // ---- phase 2: Y^T[32c][128k] += P^T @ X, combo-major issue ----
#pragma unroll
        for (int ns = 0; ns < 8; ++ns) {
            int n0 = ns * 16;
            uint32_t aaddr = sb + SM_PH + (uint32_t)(m0c + (l & 15)) * (XST * 2)
                           + n0 * 2 + (l >> 4) * 16;
            uint32_t ah[4], al[4];
            ldsm_x4(aaddr, ah);
            ldsm_x4(aaddr + (SM_PL - SM_PH), al);
            int k0 = kw * 32;
            uint32_t b0addr = sb + SM_XH + (uint32_t)(n0 + (l & 15)) * (XST * 2)
                            + (k0 + 8 * (l >> 4)) * 2;
            uint32_t b1addr = b0addr + 32;   // +16 columns (bf16)
            uint32_t bh0[4], bl0[4], bh1[4], bl1[4];
            ldsm_x4t(b0addr, bh0);
            ldsm_x4t(b0addr + (SM_XL - SM_XH), bl0);
            ldsm_x4t(b1addr, bh1);
            ldsm_x4t(b1addr + (SM_XL - SM_XH), bl1);
            // hh burst
            mma_bf16(c2[0], ah, bh0[0], bh0[1]);
            mma_bf16(c2[1], ah, bh0[2], bh0[3]);
            mma_bf16(c2[2], ah, bh1[0], bh1[1]);
            mma_bf16(c2[3], ah, bh1[2], bh1[3]);
            // hl burst
            mma_bf16(c2[0], ah, bl0[0], bl0[1]);
            mma_bf16(c2[1], ah, bl0[2], bl0[3]);
            mma_bf16(c2[2], ah, bl1[0], bl1[1]);
            mma_bf16(c2[3], ah, bl1[2], bl1[3]);
            // lh burst -> separate bank
            mma_bf16(c2b[0], al, bh0[0], bh0[1]);
            mma_bf16(c2b[1], al, bh0[2], bh0[3]);
            mma_bf16(c2b[2], al, bh1[0], bh1[1]);
            mma_bf16(c2b[3], al, bh1[2], bh1[3]);
        }
    }

    // ---- write y partial (merge lh bank here) ----
    {
        float* yo = &g_ypart[b][tile][0];
        int cr = m0c + (l >> 2);
#pragma unroll
        for (int j = 0; j < 4; ++j) {
            int k = kw * 32 + j * 8 + (l & 3) * 2;
            yo[cr * KDIM + k]           = c2[j][0] + c2b[j][0];
            yo[cr * KDIM + k + 1]       = c2[j][1] + c2b[j][1];
            yo[(cr + 8) * KDIM + k]     = c2[j][2] + c2b[j][2];
            yo[(cr + 8) * KDIM + k + 1] = c2[j][3] + c2b[j][3];
        }
    }
}

// ============================================================
// Kernel 4: sum NTILES y partials (float4). grid (2, BATCH), 512 thr.
// ============================================================
__global__ void k_yred() {
    int b = blockIdx.y, t = threadIdx.x;
    int i4 = blockIdx.x * 512 + t;
    float4 s = make_float4(0.f, 0.f, 0.f, 0.f);
#pragma unroll
    for (int p = 0; p < NTILES; ++p) {
        float4 v = ((const float4*)g_ypart[b][p])[i4];
        s.x += v.x; s.y += v.y; s.z += v.z; s.w += v.w;
    }
    ((float4*)g_y[b])[i4] = s;
}

// ============================================================
// Kernel 5: u = y @ kernel (exact fp32), squash; output or fused W2+split.
// grid 128, 512 thr.
// ============================================================
__global__ void k_fin(const float* __restrict__ w, float* __restrict__ out) {
    int b = blockIdx.x, t = threadIdx.x;
    __shared__ float ys[CAPS * KDIM];
    __shared__ float os[MCOLS];
#pragma unroll
    for (int i = 0; i < 8; ++i) ys[t + i * 512] = g_y[b][t + i * 512];
    __syncthreads();
    int c = t >> 4;
    const float* yr = &ys[c * KDIM];
    float acc = 0.f;
#pragma unroll 8
    for (int k = 0; k < KDIM; ++k) acc += yr[k] * w[k * MCOLS + t];
    float sq = acc * acc;
#pragma unroll
    for (int off = 8; off >= 1; off >>= 1)
        sq += __shfl_xor_sync(0xffffffffu, sq, off, 16);
    float s2 = sq + 1e-7f;
    float scale = sqrtf(s2) / (0.5f + s2);
    float val = scale * acc;
    if (out) {
        out[b * MCOLS + t] = val;
    } else {
        os[t] = val;
        __syncthreads();
        compute_W2(b, t, os, w);
    }
}

extern "C" void kernel_launch(void* const* d_in, const int* in_sizes, int n_in,
                              void* d_out, int out_size) {
    const float* x = (const float*)d_in[0];
    const float* w = (const float*)d_in[1];
    if (n_in >= 2 && in_sizes[0] == MCOLS * KDIM) {
        x = (const float*)d_in[1];
        w = (const float*)d_in[0];
    }
    (void)out_size;

    cudaFuncSetAttribute(k_iter_mma, cudaFuncAttributeMaxDynamicSharedMemorySize,
                         SM_TOTAL);

    k_reduce<<<dim3(NT_R, BATCH), 256>>>(x);
    k_o_first<<<BATCH, 512>>>(w);

    for (int r = 0; r < 2; ++r) {
        k_iter_mma<<<dim3(NTILES, BATCH), 256, SM_TOTAL>>>(x);
        k_yred<<<dim3(2, BATCH), 512>>>();
        k_fin<<<BATCH, 512>>>(w, (r == 1) ? (float*)d_out : nullptr);
    }
}

// round 10
// speedup vs baseline: 1.5478x; 1.0460x over previous
#include <cuda_runtime.h>
#include <cuda_bf16.h>
#include <cstdint>

#define BATCH 128
#define SEQ   2048
#define KDIM  128
#define CAPS  32
#define DCAP  16
#define MCOLS 512
#define NTILES 8          // CTAs per batch; each CTA covers 256 rows
#define NPART 16          // y partial slots = tile*2 + half

#define XST 136           // x tile stride (u16): 272B rows, ldsm conflict-free
#define PST 72            // P^T stride (u16): 144B rows, ldsm conflict-free
// smem byte offsets
#define SM_XH 0           // [2 halves][64][XST] bf16 hi
#define SM_XL 34816       // lo
#define SM_WH 69632       // [32][XST] bf16 hi
#define SM_WL 78336
#define SM_PH 87040       // [2 halves][32][PST] bf16 hi
#define SM_PL 96256
#define SM_TOTAL 105472

__device__ __forceinline__ uint32_t smem_u32(const void* p) {
    uint32_t a;
    asm("{ .reg .u64 t; cvta.to.shared.u64 t, %1; cvt.u32.u64 %0, t; }"
        : "=r"(a) : "l"(p));
    return a;
}
__device__ __forceinline__ void ldsm_x4(uint32_t a, uint32_t r[4]) {
    asm volatile("ldmatrix.sync.aligned.m8n8.x4.shared.b16 {%0,%1,%2,%3}, [%4];"
        : "=r"(r[0]), "=r"(r[1]), "=r"(r[2]), "=r"(r[3]) : "r"(a));
}
__device__ __forceinline__ void ldsm_x4t(uint32_t a, uint32_t r[4]) {
    asm volatile("ldmatrix.sync.aligned.m8n8.x4.trans.shared.b16 {%0,%1,%2,%3}, [%4];"
        : "=r"(r[0]), "=r"(r[1]), "=r"(r[2]), "=r"(r[3]) : "r"(a));
}
__device__ __forceinline__ void mma_bf16(float c[4], const uint32_t a[4],
                                         uint32_t b0, uint32_t b1) {
    asm volatile("mma.sync.aligned.m16n8k16.row.col.f32.bf16.bf16.f32 "
        "{%0,%1,%2,%3}, {%4,%5,%6,%7}, {%8,%9}, {%0,%1,%2,%3};"
        : "+f"(c[0]), "+f"(c[1]), "+f"(c[2]), "+f"(c[3])
        : "r"(a[0]), "r"(a[1]), "r"(a[2]), "r"(a[3]), "r"(b0), "r"(b1));
}
// packed bf16x2 convert: lo -> low half, hi -> high half
__device__ __forceinline__ uint32_t cvt2(float lo, float hi) {
    uint32_t r;
    asm("cvt.rn.bf16x2.f32 %0, %1, %2;" : "=r"(r) : "f"(hi), "f"(lo));
    return r;
}
#define BARH(id) asm volatile("bar.sync %0, 128;" :: "r"(id) : "memory")

// ---- scratch ----
__device__ float g_W2[BATCH][CAPS][KDIM];
__device__ unsigned short g_W2h[BATCH][CAPS * XST];
__device__ unsigned short g_W2l[BATCH][CAPS * XST];
__device__ float g_ypart[BATCH][NPART][CAPS * KDIM];

// ---- W2[b][c][k] = sum_d kernel[k, c*16+d] * o[b,c,d]; + bf16 hi/lo split ----
// call with threads t < 512 doing work (all threads must pass barriers outside)
__device__ __forceinline__ void compute_W2(int b, int t, const float* os,
                                           const float* __restrict__ w) {
#pragma unroll
    for (int i = 0; i < 8; ++i) {
        int idx = t + i * 512;
        int c = idx >> 7, k = idx & 127;
        const float4* wr = (const float4*)(w + k * MCOLS + c * DCAP);
        const float4* ov = (const float4*)(os + c * DCAP);
        float acc = 0.f;
#pragma unroll
        for (int q = 0; q < 4; ++q) {
            float4 a = wr[q], o4 = ov[q];
            acc += a.x * o4.x + a.y * o4.y + a.z * o4.z + a.w * o4.w;
        }
        g_W2[b][c][k] = acc;
        __nv_bfloat16 hh = __float2bfloat16(acc);
        __nv_bfloat16 ll = __float2bfloat16(acc - __bfloat162float(hh));
        g_W2h[b][c * XST + k] = __bfloat16_as_ushort(hh);
        g_W2l[b][c * XST + k] = __bfloat16_as_ushort(ll);
    }
}

// ============================================================
// Kernel 1: column sums of x + o1 + W2, one CTA per batch. 1024 thr.
// ============================================================
__global__ void __launch_bounds__(1024) k_init(const float* __restrict__ x,
                                               const float* __restrict__ w) {
    int b = blockIdx.x, t = threadIdx.x;
    __shared__ float4 red[32][32];
    __shared__ float S[KDIM];
    __shared__ float os[MCOLS];

    int c4 = t & 31, rg = t >> 5;
    const float4* xp = (const float4*)(x + (size_t)b * SEQ * KDIM);
    float4 s = make_float4(0.f, 0.f, 0.f, 0.f);
#pragma unroll 8
    for (int j = 0; j < 64; ++j) {
        float4 v = xp[(rg + 32 * j) * 32 + c4];
        s.x += v.x; s.y += v.y; s.z += v.z; s.w += v.w;
    }
    red[rg][c4] = s;
    __syncthreads();
    if (t < KDIM) {
        int cc = t >> 2, comp = t & 3;
        float acc = 0.f;
#pragma unroll
        for (int r = 0; r < 32; ++r) acc += ((const float*)&red[r][cc])[comp];
        S[t] = acc * (1.f / 32.f);
    }
    __syncthreads();
    if (t < 512) {
        float acc = 0.f;
#pragma unroll 4
        for (int k = 0; k < KDIM; ++k) acc += S[k] * w[k * MCOLS + t];
        float sq = acc * acc;
#pragma unroll
        for (int off = 8; off >= 1; off >>= 1)
            sq += __shfl_xor_sync(0xffffffffu, sq, off, 16);
        float s2 = sq + 1e-7f;
        float scale = sqrtf(s2) / (0.5f + s2);
        os[t] = scale * acc;
    }
    __syncthreads();
    if (t < 512) compute_W2(b, t, os, w);
}

// ============================================================
// Kernel 2: routing iteration — two independent 128-thread halves per CTA,
// each running its own 64-row subtile pipeline (named barriers).
// grid (NTILES, BATCH), 256 thr.
// ============================================================
__global__ void __launch_bounds__(256, 2) k_iter_mma(const float* __restrict__ x) {
    extern __shared__ char sm[];
    uint32_t sb = smem_u32(sm);
    int b = blockIdx.y, tile = blockIdx.x, t = threadIdx.x;
    int wid = t >> 5, l = t & 31;
    int h = wid >> 2, wl = wid & 3;
    int barid = 1 + h;
    int ht = t & 127;

    // cooperative W tile load (all 256 threads)
    {
        const uint32_t* wh = (const uint32_t*)g_W2h[b];
        const uint32_t* wls = (const uint32_t*)g_W2l[b];
        uint32_t* swh = (uint32_t*)(sm + SM_WH);
        uint32_t* swl = (uint32_t*)(sm + SM_WL);
        for (int i = t; i < CAPS * XST / 2; i += 256) {
            swh[i] = wh[i]; swl[i] = wls[i];
        }
    }
    __syncthreads();

    uint32_t xh_base = sb + SM_XH + (uint32_t)h * 64 * XST * 2;
    uint32_t ph_elem = (uint32_t)h * 32 * PST;   // u16 index base of half's P tile

    int cw = wl & 1, kw = wl >> 1;
    int m0c = cw * 16;
    int m0 = wl * 16;
    float c2[8][4];
#pragma unroll
    for (int j = 0; j < 8; ++j)
#pragma unroll
        for (int e = 0; e < 4; ++e) c2[j][e] = 0.f;

    for (int sub = 0; sub < 2; ++sub) {
        BARH(barid);   // x & P buffers free (prev subtile phase-2 done)

        // ---- load 64-row x subtile, split bf16 hi/lo (packed cvt) ----
        {
            const float4* xb = (const float4*)(
                x + ((size_t)(b * SEQ + tile * 256 + h * 128 + sub * 64)) * KDIM);
            uint32_t* xhp = (uint32_t*)(sm + SM_XH) + h * 64 * XST / 2;
            uint32_t* xlp = (uint32_t*)(sm + SM_XL) + h * 64 * XST / 2;
#pragma unroll
            for (int i = 0; i < 16; ++i) {
                int lin = ht + i * 128;
                int row = lin >> 5, c4 = lin & 31;
                float4 v = xb[row * 32 + c4];
                uint32_t h01 = cvt2(v.x, v.y);
                uint32_t h23 = cvt2(v.z, v.w);
                float f0 = __uint_as_float(h01 << 16);
                float f1 = __uint_as_float(h01 & 0xFFFF0000u);
                float f2 = __uint_as_float(h23 << 16);
                float f3 = __uint_as_float(h23 & 0xFFFF0000u);
                uint32_t l01 = cvt2(v.x - f0, v.y - f1);
                uint32_t l23 = cvt2(v.z - f2, v.w - f3);
                int u = (row * XST + c4 * 4) >> 1;
                *(uint2*)&xhp[u] = make_uint2(h01, h23);
                *(uint2*)&xlp[u] = make_uint2(l01, l23);
            }
        }
        BARH(barid);   // x ready

        // ---- phase 1: logits[64n][32c] = X @ W2^T (3 combos) ----
        float c1[4][4];
#pragma unroll
        for (int j = 0; j < 4; ++j)
#pragma unroll
            for (int e = 0; e < 4; ++e) c1[j][e] = 0.f;

#pragma unroll
        for (int ks = 0; ks < 8; ++ks) {
            int k0 = ks * 16;
            uint32_t aaddr = xh_base + (uint32_t)(m0 + (l & 15)) * (XST * 2)
                           + k0 * 2 + (l >> 4) * 16;
            uint32_t ah[4], al[4];
            ldsm_x4(aaddr, ah);
            ldsm_x4(aaddr + (SM_XL - SM_XH), al);
            uint32_t b0addr = sb + SM_WH
                + (uint32_t)((l >> 4) * 8 + (l & 7)) * (XST * 2)
                + k0 * 2 + ((l >> 3) & 1) * 16;
            uint32_t b1addr = b0addr + 16 * (XST * 2);
            uint32_t bh0[4], bl0[4], bh1[4], bl1[4];
            ldsm_x4(b0addr, bh0);
            ldsm_x4(b0addr + (SM_WL - SM_WH), bl0);
            ldsm_x4(b1addr, bh1);
            ldsm_x4(b1addr + (SM_WL - SM_WH), bl1);
            mma_bf16(c1[0], ah, bh0[0], bh0[1]);
            mma_bf16(c1[1], ah, bh0[2], bh0[3]);
            mma_bf16(c1[2], ah, bh1[0], bh1[1]);
            mma_bf16(c1[3], ah, bh1[2], bh1[3]);
            mma_bf16(c1[0], ah, bl0[0], bl0[1]);
            mma_bf16(c1[1], ah, bl0[2], bl0[3]);
            mma_bf16(c1[2], ah, bl1[0], bl1[1]);
            mma_bf16(c1[3], ah, bl1[2], bl1[3]);
            mma_bf16(c1[0], al, bh0[0], bh0[1]);
            mma_bf16(c1[1], al, bh0[2], bh0[3]);
            mma_bf16(c1[2], al, bh1[0], bh1[1]);
            mma_bf16(c1[3], al, bh1[2], bh1[3]);
        }

        // ---- softmax over 32 capsules per row; write P^T hi/lo ----
        {
            float mx0 = -1e30f, mx1 = -1e30f;
#pragma unroll
            for (int j = 0; j < 4; ++j) {
                mx0 = fmaxf(mx0, fmaxf(c1[j][0], c1[j][1]));
                mx1 = fmaxf(mx1, fmaxf(c1[j][2], c1[j][3]));
            }
            mx0 = fmaxf(mx0, __shfl_xor_sync(0xffffffffu, mx0, 1));
            mx0 = fmaxf(mx0, __shfl_xor_sync(0xffffffffu, mx0, 2));
            mx1 = fmaxf(mx1, __shfl_xor_sync(0xffffffffu, mx1, 1));
            mx1 = fmaxf(mx1, __shfl_xor_sync(0xffffffffu, mx1, 2));
            float s0 = 0.f, s1 = 0.f;
#pragma unroll
            for (int j = 0; j < 4; ++j) {
                c1[j][0] = __expf(c1[j][0] - mx0); s0 += c1[j][0];
                c1[j][1] = __expf(c1[j][1] - mx0); s0 += c1[j][1];
                c1[j][2] = __expf(c1[j][2] - mx1); s1 += c1[j][2];
                c1[j][3] = __expf(c1[j][3] - mx1); s1 += c1[j][3];
            }
            s0 += __shfl_xor_sync(0xffffffffu, s0, 1);
            s0 += __shfl_xor_sync(0xffffffffu, s0, 2);
            s1 += __shfl_xor_sync(0xffffffffu, s1, 1);
            s1 += __shfl_xor_sync(0xffffffffu, s1, 2);
            float i0 = 1.f / s0, i1 = 1.f / s1;

            unsigned short* ph = (unsigned short*)(sm + SM_PH) + ph_elem;
            unsigned short* pl = (unsigned short*)(sm + SM_PL) + ph_elem;
            int n = m0 + (l >> 2);
#pragma unroll
            for (int j = 0; j < 4; ++j) {
#pragma unroll
                for (int e = 0; e < 2; ++e) {
                    int c = j * 8 + (l & 3) * 2 + e;
                    float p0 = c1[j][e] * i0;
                    float p1 = c1[j][2 + e] * i1;
                    __nv_bfloat16 h0 = __float2bfloat16(p0);
                    __nv_bfloat16 h1 = __float2bfloat16(p1);
                    ph[c * PST + n]     = __bfloat16_as_ushort(h0);
                    ph[c * PST + n + 8] = __bfloat16_as_ushort(h1);
                    pl[c * PST + n] = __bfloat16_as_ushort(
                        __float2bfloat16(p0 - __bfloat162float(h0)));
                    pl[c * PST + n + 8] = __bfloat16_as_ushort(
                        __float2bfloat16(p1 - __bfloat162float(h1)));
                }
            }
        }
        BARH(barid);   // P ready

        // ---- phase 2: Y^T[16c][64k per warp] += P^T @ X ----
#pragma unroll
        for (int ns = 0; ns < 4; ++ns) {
            int n0 = ns * 16;
            uint32_t aaddr = sb + SM_PH
                + (ph_elem + (uint32_t)(m0c + (l & 15)) * PST) * 2
                + n0 * 2 + (l >> 4) * 16;
            uint32_t ah[4], al[4];
            ldsm_x4(aaddr, ah);
            ldsm_x4(aaddr + (SM_PL - SM_PH), al);
            uint32_t bh[4][4], bl[4][4];
#pragma unroll
            for (int q = 0; q < 4; ++q) {
                int k0 = kw * 64 + q * 16;
                uint32_t baddr = xh_base + (uint32_t)(n0 + (l & 15)) * (XST * 2)
                               + (k0 + 8 * (l >> 4)) * 2;
                ldsm_x4t(baddr, bh[q]);
                ldsm_x4t(baddr + (SM_XL - SM_XH), bl[q]);
            }
#pragma unroll
            for (int q = 0; q < 4; ++q) {
                mma_bf16(c2[2 * q],     ah, bh[q][0], bh[q][1]);
                mma_bf16(c2[2 * q + 1], ah, bh[q][2], bh[q][3]);
            }
#pragma unroll
            for (int q = 0; q < 4; ++q) {
                mma_bf16(c2[2 * q],     ah, bl[q][0], bl[q][1]);
                mma_bf16(c2[2 * q + 1], ah, bl[q][2], bl[q][3]);
            }
#pragma unroll
            for (int q = 0; q < 4; ++q) {
                mma_bf16(c2[2 * q],     al, bh[q][0], bh[q][1]);
                mma_bf16(c2[2 * q + 1], al, bh[q][2], bh[q][3]);
            }
        }
    }

    // ---- write y partial: slot = tile*2 + h ----
    {
        float* yo = &g_ypart[b][tile * 2 + h][0];
        int cr = m0c + (l >> 2);
#pragma unroll
        for (int q = 0; q < 4; ++q) {
            int k = kw * 64 + q * 16 + (l & 3) * 2;
            yo[cr * KDIM + k]            = c2[2 * q][0];
            yo[cr * KDIM + k + 1]        = c2[2 * q][1];
            yo[(cr + 8) * KDIM + k]      = c2[2 * q][2];
            yo[(cr + 8) * KDIM + k + 1]  = c2[2 * q][3];
            yo[cr * KDIM + k + 8]        = c2[2 * q + 1][0];
            yo[cr * KDIM + k + 9]        = c2[2 * q + 1][1];
            yo[(cr + 8) * KDIM + k + 8]  = c2[2 * q + 1][2];
            yo[(cr + 8) * KDIM + k + 9]  = c2[2 * q + 1][3];
        }
    }
}

// ============================================================
// Kernel 3: sum 16 y partials, u = y @ kernel, squash; output or fused W2.
// grid 128, 512 thr.
// ============================================================
__global__ void k_fin(const float* __restrict__ w, float* __restrict__ out) {
    int b = blockIdx.x, t = threadIdx.x;
    __shared__ float ys[CAPS * KDIM];
    __shared__ float os[MCOLS];
#pragma unroll
    for (int i = 0; i < 8; ++i) {
        int idx = t + i * 512;
        float s = 0.f;
#pragma unroll
        for (int p = 0; p < NPART; ++p) s += g_ypart[b][p][idx];
        ys[idx] = s;
    }
    __syncthreads();
    int c = t >> 4;
    const float* yr = &ys[c * KDIM];
    float acc = 0.f;
#pragma unroll 8
    for (int k = 0; k < KDIM; ++k) acc += yr[k] * w[k * MCOLS + t];
    float sq = acc * acc;
#pragma unroll
    for (int off = 8; off >= 1; off >>= 1)
        sq += __shfl_xor_sync(0xffffffffu, sq, off, 16);
    float s2 = sq + 1e-7f;
    float scale = sqrtf(s2) / (0.5f + s2);
    float val = scale * acc;
    if (out) {
        out[b * MCOLS + t] = val;
    } else {
        os[t] = val;
        __syncthreads();
        compute_W2(b, t, os, w);
    }
}

extern "C" void kernel_launch(void* const* d_in, const int* in_sizes, int n_in,
                              void* d_out, int out_size) {
    const float* x = (const float*)d_in[0];
    const float* w = (const float*)d_in[1];
    if (n_in >= 2 && in_sizes[0] == MCOLS * KDIM) {
        x = (const float*)d_in[1];
        w = (const float*)d_in[0];
    }
    (void)out_size;

    cudaFuncSetAttribute(k_iter_mma, cudaFuncAttributeMaxDynamicSharedMemorySize,
                         SM_TOTAL);

    k_init<<<BATCH, 1024>>>(x, w);

    for (int r = 0; r < 2; ++r) {
        k_iter_mma<<<dim3(NTILES, BATCH), 256, SM_TOTAL>>>(x);
        k_fin<<<BATCH, 512>>>(w, (r == 1) ? (float*)d_out : nullptr);
    }
}

// round 11
// speedup vs baseline: 1.5480x; 1.0001x over previous
#include <cuda_runtime.h>
#include <cuda_bf16.h>
#include <cstdint>

#define BATCH 128
#define SEQ   2048
#define KDIM  128
#define CAPS  32
#define DCAP  16
#define MCOLS 512
#define NTILES 8          // CTAs per batch; each CTA covers 256 rows
#define NPART 16          // y partial slots = tile*2 + half
#define NSUB  4           // 32-row subtiles per 128-row half

#define XST 136           // x tile stride (u16): 272B rows, ldsm conflict-free
#define PST 40            // P^T stride (u16): 80B rows, ldsm conflict-free
// smem byte offsets
#define SM_XH 0           // [2 halves][32][XST] bf16 hi
#define SM_XL 17408       // lo
#define SM_WH 34816       // [32][XST] bf16 hi
#define SM_WL 43520
#define SM_PH 52224       // [2 halves][32c][PST] bf16 hi
#define SM_PL 57344
#define SM_SX 62464       // softmax row-sum exchange [2][2][32] float
#define SM_TOTAL 62976

__device__ __forceinline__ uint32_t smem_u32(const void* p) {
    uint32_t a;
    asm("{ .reg .u64 t; cvta.to.shared.u64 t, %1; cvt.u32.u64 %0, t; }"
        : "=r"(a) : "l"(p));
    return a;
}
__device__ __forceinline__ void ldsm_x4(uint32_t a, uint32_t r[4]) {
    asm volatile("ldmatrix.sync.aligned.m8n8.x4.shared.b16 {%0,%1,%2,%3}, [%4];"
        : "=r"(r[0]), "=r"(r[1]), "=r"(r[2]), "=r"(r[3]) : "r"(a));
}
__device__ __forceinline__ void ldsm_x4t(uint32_t a, uint32_t r[4]) {
    asm volatile("ldmatrix.sync.aligned.m8n8.x4.trans.shared.b16 {%0,%1,%2,%3}, [%4];"
        : "=r"(r[0]), "=r"(r[1]), "=r"(r[2]), "=r"(r[3]) : "r"(a));
}
__device__ __forceinline__ void mma_bf16(float c[4], const uint32_t a[4],
                                         uint32_t b0, uint32_t b1) {
    asm volatile("mma.sync.aligned.m16n8k16.row.col.f32.bf16.bf16.f32 "
        "{%0,%1,%2,%3}, {%4,%5,%6,%7}, {%8,%9}, {%0,%1,%2,%3};"
        : "+f"(c[0]), "+f"(c[1]), "+f"(c[2]), "+f"(c[3])
        : "r"(a[0]), "r"(a[1]), "r"(a[2]), "r"(a[3]), "r"(b0), "r"(b1));
}
__device__ __forceinline__ uint32_t cvt2(float lo, float hi) {
    uint32_t r;
    asm("cvt.rn.bf16x2.f32 %0, %1, %2;" : "=r"(r) : "f"(hi), "f"(lo));
    return r;
}
#define BARH(id) asm volatile("bar.sync %0, 128;" :: "r"(id) : "memory")

// ---- scratch ----
__device__ float g_W2[BATCH][CAPS][KDIM];
__device__ unsigned short g_W2h[BATCH][CAPS * XST];
__device__ unsigned short g_W2l[BATCH][CAPS * XST];
__device__ float g_ypart[BATCH][NPART][CAPS * KDIM];

// ---- W2[b][c][k] = sum_d kernel[k, c*16+d] * o[b,c,d]; + bf16 hi/lo split ----
__device__ __forceinline__ void compute_W2(int b, int t, const float* os,
                                           const float* __restrict__ w) {
#pragma unroll
    for (int i = 0; i < 8; ++i) {
        int idx = t + i * 512;
        int c = idx >> 7, k = idx & 127;
        const float4* wr = (const float4*)(w + k * MCOLS + c * DCAP);
        const float4* ov = (const float4*)(os + c * DCAP);
        float acc = 0.f;
#pragma unroll
        for (int q = 0; q < 4; ++q) {
            float4 a = wr[q], o4 = ov[q];
            acc += a.x * o4.x + a.y * o4.y + a.z * o4.z + a.w * o4.w;
        }
        g_W2[b][c][k] = acc;
        __nv_bfloat16 hh = __float2bfloat16(acc);
        __nv_bfloat16 ll = __float2bfloat16(acc - __bfloat162float(hh));
        g_W2h[b][c * XST + k] = __bfloat16_as_ushort(hh);
        g_W2l[b][c * XST + k] = __bfloat16_as_ushort(ll);
    }
}

// ============================================================
// Kernel 1: column sums of x + o1 + W2, one CTA per batch. 1024 thr.
// ============================================================
__global__ void __launch_bounds__(1024) k_init(const float* __restrict__ x,
                                               const float* __restrict__ w) {
    int b = blockIdx.x, t = threadIdx.x;
    __shared__ float4 red[32][32];
    __shared__ float S[KDIM];
    __shared__ float os[MCOLS];

    int c4 = t & 31, rg = t >> 5;
    const float4* xp = (const float4*)(x + (size_t)b * SEQ * KDIM);
    float4 s = make_float4(0.f, 0.f, 0.f, 0.f);
#pragma unroll 8
    for (int j = 0; j < 64; ++j) {
        float4 v = xp[(rg + 32 * j) * 32 + c4];
        s.x += v.x; s.y += v.y; s.z += v.z; s.w += v.w;
    }
    red[rg][c4] = s;
    __syncthreads();
    if (t < KDIM) {
        int cc = t >> 2, comp = t & 3;
        float acc = 0.f;
#pragma unroll
        for (int r = 0; r < 32; ++r) acc += ((const float*)&red[r][cc])[comp];
        S[t] = acc * (1.f / 32.f);
    }
    __syncthreads();
    if (t < 512) {
        float acc = 0.f;
#pragma unroll 4
        for (int k = 0; k < KDIM; ++k) acc += S[k] * w[k * MCOLS + t];
        float sq = acc * acc;
#pragma unroll
        for (int off = 8; off >= 1; off >>= 1)
            sq += __shfl_xor_sync(0xffffffffu, sq, off, 16);
        float s2 = sq + 1e-7f;
        float scale = sqrtf(s2) / (0.5f + s2);
        os[t] = scale * acc;
    }
    __syncthreads();
    if (t < 512) compute_W2(b, t, os, w);
}

// ============================================================
// Kernel 2: routing iteration — two independent 128-thread halves,
// 32-row subtiles, 3 CTAs/SM. grid (NTILES, BATCH), 256 thr.
// ============================================================
__global__ void __launch_bounds__(256, 3) k_iter_mma(const float* __restrict__ x) {
    extern __shared__ char sm[];
    uint32_t sb = smem_u32(sm);
    int b = blockIdx.y, tile = blockIdx.x, t = threadIdx.x;
    int wid = t >> 5, l = t & 31;
    int h = wid >> 2, wl = wid & 3;
    int barid = 1 + h;
    int ht = t & 127;

    // cooperative W tile load (all 256 threads)
    {
        const uint32_t* wh = (const uint32_t*)g_W2h[b];
        const uint32_t* wls = (const uint32_t*)g_W2l[b];
        uint32_t* swh = (uint32_t*)(sm + SM_WH);
        uint32_t* swl = (uint32_t*)(sm + SM_WL);
        for (int i = t; i < CAPS * XST / 2; i += 256) {
            swh[i] = wh[i]; swl[i] = wls[i];
        }
    }
    __syncthreads();

    uint32_t xh_base = sb + SM_XH + (uint32_t)h * 32 * XST * 2;
    uint32_t ph_u16  = (uint32_t)h * 32 * PST;   // u16 index base of half's P
    float* sx = (float*)(sm + SM_SX) + h * 64;

    // phase-1 warp mapping: rows (wl&1)*16, caps (wl>>1)*16
    int rh = wl & 1, ch = wl >> 1;
    int r0 = rh * 16, c0 = ch * 16;
    // phase-2 warp mapping: caps (wl&1)*16, k (wl>>1)*64
    int cw = wl & 1, kw = wl >> 1;
    int m0c = cw * 16;

    float c2[8][4];
#pragma unroll
    for (int j = 0; j < 8; ++j)
#pragma unroll
        for (int e = 0; e < 4; ++e) c2[j][e] = 0.f;

    for (int sub = 0; sub < NSUB; ++sub) {
        BARH(barid);   // x, P, sx buffers free (prev subtile phase-2 done)

        // ---- load 32-row x subtile, split bf16 hi/lo ----
        {
            const float4* xb = (const float4*)(
                x + ((size_t)(b * SEQ + tile * 256 + h * 128 + sub * 32)) * KDIM);
            uint32_t* xhp = (uint32_t*)(sm + SM_XH) + h * 32 * XST / 2;
            uint32_t* xlp = (uint32_t*)(sm + SM_XL) + h * 32 * XST / 2;
#pragma unroll
            for (int i = 0; i < 8; ++i) {
                int lin = ht + i * 128;
                int row = lin >> 5, c4 = lin & 31;
                float4 v = xb[row * 32 + c4];
                uint32_t h01 = cvt2(v.x, v.y);
                uint32_t h23 = cvt2(v.z, v.w);
                float f0 = __uint_as_float(h01 << 16);
                float f1 = __uint_as_float(h01 & 0xFFFF0000u);
                float f2 = __uint_as_float(h23 << 16);
                float f3 = __uint_as_float(h23 & 0xFFFF0000u);
                uint32_t l01 = cvt2(v.x - f0, v.y - f1);
                uint32_t l23 = cvt2(v.z - f2, v.w - f3);
                int u = (row * XST + c4 * 4) >> 1;
                *(uint2*)&xhp[u] = make_uint2(h01, h23);
                *(uint2*)&xlp[u] = make_uint2(l01, l23);
            }
        }
        BARH(barid);   // x ready

        // ---- phase 1: logits[16n][16c] per warp = X @ W2^T (3 combos) ----
        float c1[2][4];
#pragma unroll
        for (int j = 0; j < 2; ++j)
#pragma unroll
            for (int e = 0; e < 4; ++e) c1[j][e] = 0.f;

#pragma unroll
        for (int ks = 0; ks < 8; ++ks) {
            int k0 = ks * 16;
            uint32_t aaddr = xh_base + (uint32_t)(r0 + (l & 15)) * (XST * 2)
                           + k0 * 2 + (l >> 4) * 16;
            uint32_t ah[4], al[4];
            ldsm_x4(aaddr, ah);
            ldsm_x4(aaddr + (SM_XL - SM_XH), al);
            uint32_t baddr = sb + SM_WH
                + (uint32_t)(c0 + (l >> 4) * 8 + (l & 7)) * (XST * 2)
                + k0 * 2 + ((l >> 3) & 1) * 16;
            uint32_t bh[4], bl[4];
            ldsm_x4(baddr, bh);
            ldsm_x4(baddr + (SM_WL - SM_WH), bl);
            mma_bf16(c1[0], ah, bh[0], bh[1]);
            mma_bf16(c1[1], ah, bh[2], bh[3]);
            mma_bf16(c1[0], ah, bl[0], bl[1]);
            mma_bf16(c1[1], ah, bl[2], bl[3]);
            mma_bf16(c1[0], al, bh[0], bh[1]);
            mma_bf16(c1[1], al, bh[2], bh[3]);
        }

        // ---- softmax (no-max; exact-math identical): exp + cross-warp sums ----
        {
#pragma unroll
            for (int j = 0; j < 2; ++j)
#pragma unroll
                for (int e = 0; e < 4; ++e) c1[j][e] = __expf(c1[j][e]);
            float s0 = c1[0][0] + c1[0][1] + c1[1][0] + c1[1][1];
            float s1 = c1[0][2] + c1[0][3] + c1[1][2] + c1[1][3];
            s0 += __shfl_xor_sync(0xffffffffu, s0, 1);
            s0 += __shfl_xor_sync(0xffffffffu, s0, 2);
            s1 += __shfl_xor_sync(0xffffffffu, s1, 1);
            s1 += __shfl_xor_sync(0xffffffffu, s1, 2);
            if ((l & 3) == 0) {
                sx[ch * 32 + r0 + (l >> 2)]     = s0;
                sx[ch * 32 + r0 + (l >> 2) + 8] = s1;
            }
        }
        BARH(barid);   // sums ready

        // ---- finish softmax + write P^T hi/lo ----
        {
            int n0 = r0 + (l >> 2);
            float inv0 = 1.f / (sx[n0] + sx[32 + n0]);
            float inv1 = 1.f / (sx[n0 + 8] + sx[32 + n0 + 8]);
            unsigned short* ph = (unsigned short*)(sm + SM_PH) + ph_u16;
            unsigned short* pl = (unsigned short*)(sm + SM_PL) + ph_u16;
#pragma unroll
            for (int g = 0; g < 2; ++g) {
#pragma unroll
                for (int e = 0; e < 2; ++e) {
                    int c = c0 + g * 8 + (l & 3) * 2 + e;
                    float p0 = c1[g][e] * inv0;
                    float p1 = c1[g][2 + e] * inv1;
                    __nv_bfloat16 h0 = __float2bfloat16(p0);
                    __nv_bfloat16 h1 = __float2bfloat16(p1);
                    ph[c * PST + n0]     = __bfloat16_as_ushort(h0);
                    ph[c * PST + n0 + 8] = __bfloat16_as_ushort(h1);
                    pl[c * PST + n0] = __bfloat16_as_ushort(
                        __float2bfloat16(p0 - __bfloat162float(h0)));
                    pl[c * PST + n0 + 8] = __bfloat16_as_ushort(
                        __float2bfloat16(p1 - __bfloat162float(h1)));
                }
            }
        }
        BARH(barid);   // P ready

        // ---- phase 2: Y^T[16c][64k per warp] += P^T @ X (n=32) ----
#pragma unroll
        for (int ns = 0; ns < 2; ++ns) {
            int n0 = ns * 16;
            uint32_t aaddr = sb + SM_PH
                + (ph_u16 + (uint32_t)(m0c + (l & 15)) * PST) * 2
                + n0 * 2 + (l >> 4) * 16;
            uint32_t ah[4], al[4];
            ldsm_x4(aaddr, ah);
            ldsm_x4(aaddr + (SM_PL - SM_PH), al);
#pragma unroll
            for (int qq = 0; qq < 2; ++qq) {   // two q-chunks to bound live regs
                uint32_t bh[2][4], bl[2][4];
#pragma unroll
                for (int q = 0; q < 2; ++q) {
                    int k0 = kw * 64 + (qq * 2 + q) * 16;
                    uint32_t baddr = xh_base
                        + (uint32_t)(n0 + (l & 15)) * (XST * 2)
                        + (k0 + 8 * (l >> 4)) * 2;
                    ldsm_x4t(baddr, bh[q]);
                    ldsm_x4t(baddr + (SM_XL - SM_XH), bl[q]);
                }
#pragma unroll
                for (int q = 0; q < 2; ++q) {
                    int j = (qq * 2 + q) * 2;
                    mma_bf16(c2[j],     ah, bh[q][0], bh[q][1]);
                    mma_bf16(c2[j + 1], ah, bh[q][2], bh[q][3]);
                    mma_bf16(c2[j],     ah, bl[q][0], bl[q][1]);
                    mma_bf16(c2[j + 1], ah, bl[q][2], bl[q][3]);
                    mma_bf16(c2[j],     al, bh[q][0], bh[q][1]);
                    mma_bf16(c2[j + 1], al, bh[q][2], bh[q][3]);
                }
            }
        }
    }

    // ---- write y partial: slot = tile*2 + h ----
    {
        float* yo = &g_ypart[b][tile * 2 + h][0];
        int cr = m0c + (l >> 2);
#pragma unroll
        for (int q = 0; q < 4; ++q) {
            int k = kw * 64 + q * 16 + (l & 3) * 2;
            yo[cr * KDIM + k]            = c2[2 * q][0];
            yo[cr * KDIM + k + 1]        = c2[2 * q][1];
            yo[(cr + 8) * KDIM + k]      = c2[2 * q][2];
            yo[(cr + 8) * KDIM + k + 1]  = c2[2 * q][3];
            yo[cr * KDIM + k + 8]        = c2[2 * q + 1][0];
            yo[cr * KDIM + k + 9]        = c2[2 * q + 1][1];
            yo[(cr + 8) * KDIM + k + 8]  = c2[2 * q + 1][2];
            yo[(cr + 8) * KDIM + k + 9]  = c2[2 * q + 1][3];
        }
    }
}

// ============================================================
// Kernel 3: sum 16 y partials, u = y @ kernel, squash; output or fused W2.
// grid 128, 512 thr.
// ============================================================
__global__ void k_fin(const float* __restrict__ w, float* __restrict__ out) {
    int b = blockIdx.x, t = threadIdx.x;
    __shared__ float ys[CAPS * KDIM];
    __shared__ float os[MCOLS];
#pragma unroll
    for (int i = 0; i < 8; ++i) {
        int idx = t + i * 512;
        float s = 0.f;
#pragma unroll
        for (int p = 0; p < NPART; ++p) s += g_ypart[b][p][idx];
        ys[idx] = s;
    }
    __syncthreads();
    int c = t >> 4;
    const float* yr = &ys[c * KDIM];
    float acc = 0.f;
#pragma unroll 8
    for (int k = 0; k < KDIM; ++k) acc += yr[k] * w[k * MCOLS + t];
    float sq = acc * acc;
#pragma unroll
    for (int off = 8; off >= 1; off >>= 1)
        sq += __shfl_xor_sync(0xffffffffu, sq, off, 16);
    float s2 = sq + 1e-7f;
    float scale = sqrtf(s2) / (0.5f + s2);
    float val = scale * acc;
    if (out) {
        out[b * MCOLS + t] = val;
    } else {
        os[t] = val;
        __syncthreads();
        compute_W2(b, t, os, w);
    }
}

extern "C" void kernel_launch(void* const* d_in, const int* in_sizes, int n_in,
                              void* d_out, int out_size) {
    const float* x = (const float*)d_in[0];
    const float* w = (const float*)d_in[1];
    if (n_in >= 2 && in_sizes[0] == MCOLS * KDIM) {
        x = (const float*)d_in[1];
        w = (const float*)d_in[0];
    }
    (void)out_size;

    cudaFuncSetAttribute(k_iter_mma, cudaFuncAttributeMaxDynamicSharedMemorySize,
                         SM_TOTAL);

    k_init<<<BATCH, 1024>>>(x, w);

    for (int r = 0; r < 2; ++r) {
        k_iter_mma<<<dim3(NTILES, BATCH), 256, SM_TOTAL>>>(x);
        k_fin<<<BATCH, 512>>>(w, (r == 1) ? (float*)d_out : nullptr);
    }
}

// round 12
// speedup vs baseline: 1.5939x; 1.0296x over previous
#include <cuda_runtime.h>
#include <cuda_fp16.h>
#include <cstdint>

#define BATCH 128
#define SEQ   2048
#define KDIM  128
#define CAPS  32
#define DCAP  16
#define MCOLS 512
#define NTILES 8          // CTAs per batch; each CTA covers 256 rows
#define NPART 16          // y partial slots = tile*2 + half
#define NSUB  4           // 32-row subtiles per 128-row half

#define XST 136           // x tile stride (u16): 272B rows, ldsm conflict-free
#define PST 40            // P^T stride (u16): 80B rows, ldsm conflict-free
// smem byte offsets
#define SM_XH 0           // [2 halves][32][XST] fp16 hi
#define SM_XL 17408       // lo
#define SM_WH 34816       // [32][XST] fp16 hi
#define SM_WL 43520
#define SM_PH 52224       // [2 halves][32c][PST] fp16 (hi only)
#define SM_SX 57344       // softmax row-sum exchange [2][2][32] float
#define SM_TOTAL 57856

__device__ __forceinline__ uint32_t smem_u32(const void* p) {
    uint32_t a;
    asm("{ .reg .u64 t; cvta.to.shared.u64 t, %1; cvt.u32.u64 %0, t; }"
        : "=r"(a) : "l"(p));
    return a;
}
__device__ __forceinline__ void ldsm_x4(uint32_t a, uint32_t r[4]) {
    asm volatile("ldmatrix.sync.aligned.m8n8.x4.shared.b16 {%0,%1,%2,%3}, [%4];"
        : "=r"(r[0]), "=r"(r[1]), "=r"(r[2]), "=r"(r[3]) : "r"(a));
}
__device__ __forceinline__ void ldsm_x4t(uint32_t a, uint32_t r[4]) {
    asm volatile("ldmatrix.sync.aligned.m8n8.x4.trans.shared.b16 {%0,%1,%2,%3}, [%4];"
        : "=r"(r[0]), "=r"(r[1]), "=r"(r[2]), "=r"(r[3]) : "r"(a));
}
__device__ __forceinline__ void mma_f16(float c[4], const uint32_t a[4],
                                        uint32_t b0, uint32_t b1) {
    asm volatile("mma.sync.aligned.m16n8k16.row.col.f32.f16.f16.f32 "
        "{%0,%1,%2,%3}, {%4,%5,%6,%7}, {%8,%9}, {%0,%1,%2,%3};"
        : "+f"(c[0]), "+f"(c[1]), "+f"(c[2]), "+f"(c[3])
        : "r"(a[0]), "r"(a[1]), "r"(a[2]), "r"(a[3]), "r"(b0), "r"(b1));
}
__device__ __forceinline__ uint32_t pack_h2(__half a, __half b) {
    __half2 h = __halves2half2(a, b);
    return *(uint32_t*)&h;
}
#define BARH(id) asm volatile("bar.sync %0, 128;" :: "r"(id) : "memory")

// ---- scratch ----
__device__ float g_W2[BATCH][CAPS][KDIM];
__device__ unsigned short g_W2h[BATCH][CAPS * XST];
__device__ unsigned short g_W2l[BATCH][CAPS * XST];
__device__ float g_ypart[BATCH][NPART][CAPS * KDIM];

// ---- W2[b][c][k] = sum_d kernel[k, c*16+d] * o[b,c,d]; + fp16 hi/lo split ----
__device__ __forceinline__ void compute_W2(int b, int t, const float* os,
                                           const float* __restrict__ w) {
#pragma unroll
    for (int i = 0; i < 8; ++i) {
        int idx = t + i * 512;
        int c = idx >> 7, k = idx & 127;
        const float4* wr = (const float4*)(w + k * MCOLS + c * DCAP);
        const float4* ov = (const float4*)(os + c * DCAP);
        float acc = 0.f;
#pragma unroll
        for (int q = 0; q < 4; ++q) {
            float4 a = wr[q], o4 = ov[q];
            acc += a.x * o4.x + a.y * o4.y + a.z * o4.z + a.w * o4.w;
        }
        g_W2[b][c][k] = acc;
        __half hh = __float2half_rn(acc);
        __half ll = __float2half_rn(acc - __half2float(hh));
        g_W2h[b][c * XST + k] = *(unsigned short*)&hh;
        g_W2l[b][c * XST + k] = *(unsigned short*)&ll;
    }
}

// ============================================================
// Kernel 1: column sums of x + o1 + W2, one CTA per batch. 1024 thr.
// ============================================================
__global__ void __launch_bounds__(1024) k_init(const float* __restrict__ x,
                                               const float* __restrict__ w) {
    int b = blockIdx.x, t = threadIdx.x;
    __shared__ float4 red[32][32];
    __shared__ float S[KDIM];
    __shared__ float os[MCOLS];

    int c4 = t & 31, rg = t >> 5;
    const float4* xp = (const float4*)(x + (size_t)b * SEQ * KDIM);
    float4 s = make_float4(0.f, 0.f, 0.f, 0.f);
#pragma unroll 8
    for (int j = 0; j < 64; ++j) {
        float4 v = xp[(rg + 32 * j) * 32 + c4];
        s.x += v.x; s.y += v.y; s.z += v.z; s.w += v.w;
    }
    red[rg][c4] = s;
    __syncthreads();
    if (t < KDIM) {
        int cc = t >> 2, comp = t & 3;
        float acc = 0.f;
#pragma unroll
        for (int r = 0; r < 32; ++r) acc += ((const float*)&red[r][cc])[comp];
        S[t] = acc * (1.f / 32.f);
    }
    __syncthreads();
    if (t < 512) {
        float acc = 0.f;
#pragma unroll 4
        for (int k = 0; k < KDIM; ++k) acc += S[k] * w[k * MCOLS + t];
        float sq = acc * acc;
#pragma unroll
        for (int off = 8; off >= 1; off >>= 1)
            sq += __shfl_xor_sync(0xffffffffu, sq, off, 16);
        float s2 = sq + 1e-7f;
        float scale = sqrtf(s2) / (0.5f + s2);
        os[t] = scale * acc;
    }
    __syncthreads();
    if (t < 512) compute_W2(b, t, os, w);
}

// ============================================================
// Kernel 2: routing iteration — fp16 split, 2-combo phase 2.
// grid (NTILES, BATCH), 256 thr, 3 CTAs/SM.
// ============================================================
__global__ void __launch_bounds__(256, 3) k_iter_mma(const float* __restrict__ x) {
    extern __shared__ char sm[];
    uint32_t sb = smem_u32(sm);
    int b = blockIdx.y, tile = blockIdx.x, t = threadIdx.x;
    int wid = t >> 5, l = t & 31;
    int h = wid >> 2, wl = wid & 3;
    int barid = 1 + h;
    int ht = t & 127;

    // cooperative W tile load (all 256 threads)
    {
        const uint32_t* wh = (const uint32_t*)g_W2h[b];
        const uint32_t* wls = (const uint32_t*)g_W2l[b];
        uint32_t* swh = (uint32_t*)(sm + SM_WH);
        uint32_t* swl = (uint32_t*)(sm + SM_WL);
        for (int i = t; i < CAPS * XST / 2; i += 256) {
            swh[i] = wh[i]; swl[i] = wls[i];
        }
    }
    __syncthreads();

    uint32_t xh_base = sb + SM_XH + (uint32_t)h * 32 * XST * 2;
    uint32_t ph_u16  = (uint32_t)h * 32 * PST;
    float* sx = (float*)(sm + SM_SX) + h * 64;

    int rh = wl & 1, ch = wl >> 1;
    int r0 = rh * 16, c0 = ch * 16;
    int cw = wl & 1, kw = wl >> 1;
    int m0c = cw * 16;

    float c2[8][4];
#pragma unroll
    for (int j = 0; j < 8; ++j)
#pragma unroll
        for (int e = 0; e < 4; ++e) c2[j][e] = 0.f;

    for (int sub = 0; sub < NSUB; ++sub) {
        BARH(barid);   // buffers free

        // ---- load 32-row x subtile, split fp16 hi/lo (exact residuals) ----
        {
            const float4* xb = (const float4*)(
                x + ((size_t)(b * SEQ + tile * 256 + h * 128 + sub * 32)) * KDIM);
            uint32_t* xhp = (uint32_t*)(sm + SM_XH) + h * 32 * XST / 2;
            uint32_t* xlp = (uint32_t*)(sm + SM_XL) + h * 32 * XST / 2;
#pragma unroll
            for (int i = 0; i < 8; ++i) {
                int lin = ht + i * 128;
                int row = lin >> 5, c4 = lin & 31;
                float4 v = xb[row * 32 + c4];
                __half hx = __float2half_rn(v.x), hy = __float2half_rn(v.y);
                __half hz = __float2half_rn(v.z), hw = __float2half_rn(v.w);
                uint32_t h01 = pack_h2(hx, hy);
                uint32_t h23 = pack_h2(hz, hw);
                uint32_t l01 = pack_h2(__float2half_rn(v.x - __half2float(hx)),
                                       __float2half_rn(v.y - __half2float(hy)));
                uint32_t l23 = pack_h2(__float2half_rn(v.z - __half2float(hz)),
                                       __float2half_rn(v.w - __half2float(hw)));
                int u = (row * XST + c4 * 4) >> 1;
                *(uint2*)&xhp[u] = make_uint2(h01, h23);
                *(uint2*)&xlp[u] = make_uint2(l01, l23);
            }
        }
        BARH(barid);   // x ready

        // ---- phase 1: logits[16n][16c] per warp = X @ W2^T (3 combos) ----
        float c1[2][4];
#pragma unroll
        for (int j = 0; j < 2; ++j)
#pragma unroll
            for (int e = 0; e < 4; ++e) c1[j][e] = 0.f;

#pragma unroll
        for (int ks = 0; ks < 8; ++ks) {
            int k0 = ks * 16;
            uint32_t aaddr = xh_base + (uint32_t)(r0 + (l & 15)) * (XST * 2)
                           + k0 * 2 + (l >> 4) * 16;
            uint32_t ah[4], al[4];
            ldsm_x4(aaddr, ah);
            ldsm_x4(aaddr + (SM_XL - SM_XH), al);
            uint32_t baddr = sb + SM_WH
                + (uint32_t)(c0 + (l >> 4) * 8 + (l & 7)) * (XST * 2)
                + k0 * 2 + ((l >> 3) & 1) * 16;
            uint32_t bh[4], bl[4];
            ldsm_x4(baddr, bh);
            ldsm_x4(baddr + (SM_WL - SM_WH), bl);
            mma_f16(c1[0], ah, bh[0], bh[1]);
            mma_f16(c1[1], ah, bh[2], bh[3]);
            mma_f16(c1[0], ah, bl[0], bl[1]);
            mma_f16(c1[1], ah, bl[2], bl[3]);
            mma_f16(c1[0], al, bh[0], bh[1]);
            mma_f16(c1[1], al, bh[2], bh[3]);
        }

        // ---- softmax (no-max; exact-math identical): exp + cross-warp sums ----
        {
#pragma unroll
            for (int j = 0; j < 2; ++j)
#pragma unroll
                for (int e = 0; e < 4; ++e) c1[j][e] = __expf(c1[j][e]);
            float s0 = c1[0][0] + c1[0][1] + c1[1][0] + c1[1][1];
            float s1 = c1[0][2] + c1[0][3] + c1[1][2] + c1[1][3];
            s0 += __shfl_xor_sync(0xffffffffu, s0, 1);
            s0 += __shfl_xor_sync(0xffffffffu, s0, 2);
            s1 += __shfl_xor_sync(0xffffffffu, s1, 1);
            s1 += __shfl_xor_sync(0xffffffffu, s1, 2);
            if ((l & 3) == 0) {
                sx[ch * 32 + r0 + (l >> 2)]     = s0;
                sx[ch * 32 + r0 + (l >> 2) + 8] = s1;
            }
        }
        BARH(barid);   // sums ready

        // ---- finish softmax + write P^T (hi only) ----
        {
            int n0 = r0 + (l >> 2);
            float inv0 = 1.f / (sx[n0] + sx[32 + n0]);
            float inv1 = 1.f / (sx[n0 + 8] + sx[32 + n0 + 8]);
            unsigned short* ph = (unsigned short*)(sm + SM_PH) + ph_u16;
#pragma unroll
            for (int g = 0; g < 2; ++g) {
#pragma unroll
                for (int e = 0; e < 2; ++e) {
                    int c = c0 + g * 8 + (l & 3) * 2 + e;
                    __half h0 = __float2half_rn(c1[g][e] * inv0);
                    __half h1 = __float2half_rn(c1[g][2 + e] * inv1);
                    ph[c * PST + n0]     = *(unsigned short*)&h0;
                    ph[c * PST + n0 + 8] = *(unsigned short*)&h1;
                }
            }
        }
        BARH(barid);   // P ready

        // ---- phase 2: Y^T[16c][64k per warp] += P^T @ X (2 combos) ----
#pragma unroll
        for (int ns = 0; ns < 2; ++ns) {
            int n0 = ns * 16;
            uint32_t aaddr = sb + SM_PH
                + (ph_u16 + (uint32_t)(m0c + (l & 15)) * PST) * 2
                + n0 * 2 + (l >> 4) * 16;
            uint32_t ah[4];
            ldsm_x4(aaddr, ah);
#pragma unroll
            for (int qq = 0; qq < 2; ++qq) {
                uint32_t bh[2][4], bl[2][4];
#pragma unroll
                for (int q = 0; q < 2; ++q) {
                    int k0 = kw * 64 + (qq * 2 + q) * 16;
                    uint32_t baddr = xh_base
                        + (uint32_t)(n0 + (l & 15)) * (XST * 2)
                        + (k0 + 8 * (l >> 4)) * 2;
                    ldsm_x4t(baddr, bh[q]);
                    ldsm_x4t(baddr + (SM_XL - SM_XH), bl[q]);
                }
#pragma unroll
                for (int q = 0; q < 2; ++q) {
                    int j = (qq * 2 + q) * 2;
                    mma_f16(c2[j],     ah, bh[q][0], bh[q][1]);
                    mma_f16(c2[j + 1], ah, bh[q][2], bh[q][3]);
                    mma_f16(c2[j],     ah, bl[q][0], bl[q][1]);
                    mma_f16(c2[j + 1], ah, bl[q][2], bl[q][3]);
                }
            }
        }
    }

    // ---- write y partial: slot = tile*2 + h ----
    {
        float* yo = &g_ypart[b][tile * 2 + h][0];
        int cr = m0c + (l >> 2);
#pragma unroll
        for (int q = 0; q < 4; ++q) {
            int k = kw * 64 + q * 16 + (l & 3) * 2;
            yo[cr * KDIM + k]            = c2[2 * q][0];
            yo[cr * KDIM + k + 1]        = c2[2 * q][1];
            yo[(cr + 8) * KDIM + k]      = c2[2 * q][2];
            yo[(cr + 8) * KDIM + k + 1]  = c2[2 * q][3];
            yo[cr * KDIM + k + 8]        = c2[2 * q + 1][0];
            yo[cr * KDIM + k + 9]        = c2[2 * q + 1][1];
            yo[(cr + 8) * KDIM + k + 8]  = c2[2 * q + 1][2];
            yo[(cr + 8) * KDIM + k + 9]  = c2[2 * q + 1][3];
        }
    }
}

// ============================================================
// Kernel 3: sum 16 y partials, u = y @ kernel, squash; output or fused W2.
// grid 128, 512 thr.
// ============================================================
__global__ void k_fin(const float* __restrict__ w, float* __restrict__ out) {
    int b = blockIdx.x, t = threadIdx.x;
    __shared__ float ys[CAPS * KDIM];
    __shared__ float os[MCOLS];
#pragma unroll
    for (int i = 0; i < 8; ++i) {
        int idx = t + i * 512;
        float s = 0.f;
#pragma unroll
        for (int p = 0; p < NPART; ++p) s += g_ypart[b][p][idx];
        ys[idx] = s;
    }
    __syncthreads();
    int c = t >> 4;
    const float* yr = &ys[c * KDIM];
    float acc = 0.f;
#pragma unroll 8
    for (int k = 0; k < KDIM; ++k) acc += yr[k] * w[k * MCOLS + t];
    float sq = acc * acc;
#pragma unroll
    for (int off = 8; off >= 1; off >>= 1)
        sq += __shfl_xor_sync(0xffffffffu, sq, off, 16);
    float s2 = sq + 1e-7f;
    float scale = sqrtf(s2) / (0.5f + s2);
    float val = scale * acc;
    if (out) {
        out[b * MCOLS + t] = val;
    } else {
        os[t] = val;
        __syncthreads();
        compute_W2(b, t, os, w);
    }
}

extern "C" void kernel_launch(void* const* d_in, const int* in_sizes, int n_in,
                              void* d_out, int out_size) {
    const float* x = (const float*)d_in[0];
    const float* w = (const float*)d_in[1];
    if (n_in >= 2 && in_sizes[0] == MCOLS * KDIM) {
        x = (const float*)d_in[1];
        w = (const float*)d_in[0];
    }
    (void)out_size;

    cudaFuncSetAttribute(k_iter_mma, cudaFuncAttributeMaxDynamicSharedMemorySize,
                         SM_TOTAL);

    k_init<<<BATCH, 1024>>>(x, w);

    for (int r = 0; r < 2; ++r) {
        k_iter_mma<<<dim3(NTILES, BATCH), 256, SM_TOTAL>>>(x);
        k_fin<<<BATCH, 512>>>(w, (r == 1) ? (float*)d_out : nullptr);
    }
}